// round 14
// baseline (speedup 1.0000x reference)
#include <cuda_runtime.h>
#include <math.h>
#include <cstdint>

// ---------------- problem constants ------------------------------------------
#define BBATCH 2
#define LL 1024
#define DIN 512
#define DM 1024
#define DS 16
#define DD 64
#define KERW 4
#define TOK (BBATCH * LL)      // 2048
#define CHUNK 32
#define NCH (LL / CHUNK)       // 32
#define KSPLIT_BCD 8

// ---------------- scratch (static device globals) ----------------------------
__device__ __align__(16) float g_ab[TOK * 2 * DM];
__device__ __align__(16) float g_xr[TOK * DM];       // tf32-rounded conv output
__device__ __align__(16) float g_bcd[TOK * 96];      // atomically accumulated
__device__ __align__(16) float g_delta[TOK * DM];
__device__ __align__(16) float g_wbcd[96 * DM];
__device__ __align__(16) float g_hend[BBATCH * NCH * DS * DM];
__device__ __align__(16) float g_pd[BBATCH * NCH * DM];
__device__ __align__(16) float g_hinit[BBATCH * NCH * DS * DM];
__device__ __align__(16) float g_obuf[TOK * DM];

// ---------------- small PTX helpers ------------------------------------------
__device__ __forceinline__ uint32_t smem_u32(const void* p) {
    uint32_t a;
    asm("{ .reg .u64 t; cvta.to.shared.u64 t, %1; cvt.u32.u64 %0, t; }" : "=r"(a) : "l"(p));
    return a;
}
__device__ __forceinline__ float tf32r(float x) {
    uint32_t o;
    asm("cvt.rna.tf32.f32 %0, %1;" : "=r"(o) : "f"(x));
    return __uint_as_float(o);
}
__device__ __forceinline__ uint32_t tf32u(uint32_t x) {
    uint32_t o;
    asm("cvt.rna.tf32.f32 %0, %1;" : "=r"(o) : "f"(__uint_as_float(x)));
    return o;
}
__device__ __forceinline__ float4 tf32r4(float4 v) {
    return make_float4(tf32r(v.x), tf32r(v.y), tf32r(v.z), tf32r(v.w));
}
__device__ __forceinline__ void cp16(uint32_t dst, const void* src, int sz) {
    asm volatile("cp.async.ca.shared.global [%0], [%1], 16, %2;"
                 :: "r"(dst), "l"(src), "r"(sz) : "memory");
}
#define CP_COMMIT() asm volatile("cp.async.commit_group;" ::: "memory")
#define CP_WAIT0()  asm volatile("cp.async.wait_group 0;" ::: "memory")

// fast softplus / silu (MUFU-based intrinsics; rel err ~1e-7, far under budget)
__device__ __forceinline__ float softplus_f(float z) {
    return fmaxf(z, 0.f) + __logf(1.f + __expf(-fabsf(z)));
}
__device__ __forceinline__ float silu_f(float x) {
    return __fdividef(x, 1.f + __expf(-x));
}

__device__ __forceinline__ void mma_tf32(float* c, const uint32_t* a, uint32_t b0, uint32_t b1) {
    asm volatile(
        "mma.sync.aligned.m16n8k8.row.col.f32.tf32.tf32.f32 "
        "{%0,%1,%2,%3}, {%4,%5,%6,%7}, {%8,%9}, {%0,%1,%2,%3};"
        : "+f"(c[0]), "+f"(c[1]), "+f"(c[2]), "+f"(c[3])
        : "r"(a[0]), "r"(a[1]), "r"(a[2]), "r"(a[3]), "r"(b0), "r"(b1));
}
__device__ __forceinline__ void ldsm4(uint32_t& r0, uint32_t& r1, uint32_t& r2, uint32_t& r3,
                                      uint32_t addr) {
    asm volatile("ldmatrix.sync.aligned.m8n8.x4.shared.b16 {%0,%1,%2,%3}, [%4];"
                 : "=r"(r0), "=r"(r1), "=r"(r2), "=r"(r3) : "r"(addr));
}

// ---------------- generic tf32 GEMM:  C[M,N] = A[M,K] * W[N,K]^T -------------
// Raw fp32 inputs; fragments rounded to tf32 (RNA) in registers post-ldmatrix.
#define BMT 128
#define BKT 32
#define PADS 36

// mode: 0 = plain store, 1 = softplus(aux[col] + acc)
template <int BNT>
__global__ __launch_bounds__(256) void gemm_mma(
    const float* __restrict__ A, int lda,
    const float* __restrict__ W, int ldw,
    float* __restrict__ C, int ldc,
    int Nvalid, int T, int kstride, long cstride,
    int mode, const float* __restrict__ aux)
{
    constexpr int NT = BNT / 16;
    constexpr int stA = BMT * PADS;
    constexpr int stB = BNT * PADS;

    extern __shared__ float smem[];
    float* As = smem;
    float* Bs = smem + 2 * stA;
    const uint32_t sbA = smem_u32(As);
    const uint32_t sbB = smem_u32(Bs);

    const int tid = threadIdx.x;
    const int lane = tid & 31;
    const int wid = tid >> 5;
    const int warp_m = wid & 3;
    const int warp_n = wid >> 2;
    const int bm = blockIdx.y * BMT;
    const int bn = blockIdx.x * BNT;
    const int koff = blockIdx.z * kstride;
    C += (long)blockIdx.z * cstride;

    const int gid = lane >> 2;
    const int tig = lane & 3;
    const int grp = lane >> 3;
    const int lr  = lane & 7;

    uint32_t aoff[2];
#pragma unroll
    for (int mt = 0; mt < 2; mt++)
        aoff[mt] = (uint32_t)(((warp_m * 32 + mt * 16 + (grp & 1) * 8 + lr) * PADS
                               + (grp >> 1) * 4) * 4);
    uint32_t boff[NT / 2];
#pragma unroll
    for (int j = 0; j < NT / 2; j++)
        boff[j] = (uint32_t)(((warp_n * (BNT / 2) + (2 * j + (grp >> 1)) * 8 + lr) * PADS
                              + (grp & 1) * 4) * 4);

    float acc[2][NT][4];
#pragma unroll
    for (int mt = 0; mt < 2; mt++)
#pragma unroll
        for (int nt = 0; nt < NT; nt++)
#pragma unroll
            for (int i = 0; i < 4; i++) acc[mt][nt][i] = 0.f;

    auto load_tiles = [&](int st, int t) {
        const int kc = koff + t * BKT;
#pragma unroll
        for (int j = 0; j < (BMT * 8) / 256; j++) {
            int idx = tid + j * 256;
            int row = idx >> 3, c4 = idx & 7;
            cp16(sbA + (uint32_t)(st * stA + row * PADS + c4 * 4) * 4,
                 A + (size_t)(bm + row) * lda + kc + c4 * 4, 16);
        }
#pragma unroll
        for (int j = 0; j < (BNT * 8 + 255) / 256; j++) {
            int idx = tid + j * 256;
            if (idx < BNT * 8) {
                int row = idx >> 3, c4 = idx & 7;
                bool v = (bn + row) < Nvalid;
                cp16(sbB + (uint32_t)(st * stB + row * PADS + c4 * 4) * 4,
                     W + (size_t)(v ? bn + row : 0) * ldw + kc + c4 * 4, v ? 16 : 0);
            }
        }
    };

    load_tiles(0, 0);
    CP_COMMIT();

    for (int t = 0; t < T; t++) {
        CP_WAIT0();
        __syncthreads();
        if (t + 1 < T) { load_tiles((t + 1) & 1, t + 1); CP_COMMIT(); }

        const uint32_t abase = sbA + (uint32_t)((t & 1) * stA * 4);
        const uint32_t bbase = sbB + (uint32_t)((t & 1) * stB * 4);
#pragma unroll
        for (int k0 = 0; k0 < 4; k0++) {
            uint32_t af[2][4];
#pragma unroll
            for (int mt = 0; mt < 2; mt++) {
                ldsm4(af[mt][0], af[mt][1], af[mt][2], af[mt][3],
                      abase + aoff[mt] + k0 * 32);
#pragma unroll
                for (int i = 0; i < 4; i++) af[mt][i] = tf32u(af[mt][i]);
            }
#pragma unroll
            for (int j = 0; j < NT / 2; j++) {
                uint32_t b0, b1, b2, b3;
                ldsm4(b0, b1, b2, b3, bbase + boff[j] + k0 * 32);
                b0 = tf32u(b0); b1 = tf32u(b1); b2 = tf32u(b2); b3 = tf32u(b3);
#pragma unroll
                for (int mt = 0; mt < 2; mt++) {
                    mma_tf32(acc[mt][2 * j + 0], af[mt], b0, b1);
                    mma_tf32(acc[mt][2 * j + 1], af[mt], b2, b3);
                }
            }
        }
    }

    // ---- epilogue ----
#pragma unroll
    for (int mt = 0; mt < 2; mt++) {
#pragma unroll
        for (int nt = 0; nt < NT; nt++) {
            int r0 = bm + warp_m * 32 + mt * 16 + gid;
            int cN = bn + warp_n * (BNT / 2) + nt * 8 + 2 * tig;
            if (cN < Nvalid) {
                float v0 = acc[mt][nt][0], v1 = acc[mt][nt][1];
                float v2 = acc[mt][nt][2], v3 = acc[mt][nt][3];
                if (mode == 1) {
                    float d0 = aux[cN], d1 = aux[cN + 1];
                    v0 = softplus_f(d0 + v0);
                    v1 = softplus_f(d1 + v1);
                    v2 = softplus_f(d0 + v2);
                    v3 = softplus_f(d1 + v3);
                }
                *(float2*)&C[(size_t)r0 * ldc + cN] = make_float2(v0, v1);
                *(float2*)&C[(size_t)(r0 + 8) * ldc + cN] = make_float2(v2, v3);
            }
        }
    }
}

// ---------------- fused conv+SiLU + bcd GEMM (N=96, T=4, split-K over d) -----
#define CPAD 132
#define ST_B96 (96 * PADS)
#define SMEM_BCDCONV ((128 * CPAD + 4 * ST_B96) * 4)

__global__ __launch_bounds__(256) void gemm_bcd_conv(
    const float* __restrict__ cw, const float* __restrict__ cb)
{
    extern __shared__ float smem[];
    float* Ap = smem;                        // [128][CPAD]
    float* Bs = smem + 128 * CPAD;           // [4][96][PADS]
    const uint32_t sbA = smem_u32(Ap);
    const uint32_t sbB = smem_u32(Bs);

    const int tid = threadIdx.x;
    const int lane = tid & 31;
    const int wid = tid >> 5;
    const int warp_m = wid & 3;
    const int warp_n = wid >> 2;
    const int bm = blockIdx.y * 128;
    const int koff = blockIdx.z * (DM / KSPLIT_BCD);

    // ---- prologue: prefetch ALL 4 B k-tiles ----
#pragma unroll
    for (int t = 0; t < 4; t++) {
        const int kc = koff + t * BKT;
#pragma unroll
        for (int j = 0; j < 3; j++) {
            int idx = tid + j * 256;
            if (idx < 96 * 8) {
                int row = idx >> 3, c4 = idx & 7;
                cp16(sbB + (uint32_t)(t * ST_B96 + row * PADS + c4 * 4) * 4,
                     g_wbcd + (size_t)row * DM + kc + c4 * 4, 16);
            }
        }
        CP_COMMIT();
    }

    // ---- conv phase ----
    for (int task = tid; task < 512; task += 256) {
        int c4 = task & 31;
        int tb = task >> 5;
        int t0 = bm + tb * 8;
        int l0 = t0 & (LL - 1);
        int base = t0 - l0;
        int d = koff + c4 * 4;

        float4 cb4 = *(const float4*)(cb + d);
        float4 w0 = *(const float4*)(cw + (d + 0) * KERW);
        float4 w1 = *(const float4*)(cw + (d + 1) * KERW);
        float4 w2 = *(const float4*)(cw + (d + 2) * KERW);
        float4 w3 = *(const float4*)(cw + (d + 3) * KERW);
        float4 wk[KERW];
        wk[0] = make_float4(w0.x, w1.x, w2.x, w3.x);
        wk[1] = make_float4(w0.y, w1.y, w2.y, w3.y);
        wk[2] = make_float4(w0.z, w1.z, w2.z, w3.z);
        wk[3] = make_float4(w0.w, w1.w, w2.w, w3.w);

        float4 win[8 + KERW - 1];
#pragma unroll
        for (int j = 0; j < 8 + KERW - 1; j++) {
            int ll = l0 - (KERW - 1) + j;
            if (ll >= 0)
                win[j] = *(const float4*)(g_ab + (size_t)(base + ll) * (2 * DM) + d);
            else
                win[j] = make_float4(0.f, 0.f, 0.f, 0.f);
        }
#pragma unroll
        for (int i = 0; i < 8; i++) {
            float4 acc = cb4;
#pragma unroll
            for (int k = 0; k < KERW; k++) {
                float4 a = win[i + k];
                acc.x += a.x * wk[k].x; acc.y += a.y * wk[k].y;
                acc.z += a.z * wk[k].z; acc.w += a.w * wk[k].w;
            }
            acc.x = silu_f(acc.x); acc.y = silu_f(acc.y);
            acc.z = silu_f(acc.z); acc.w = silu_f(acc.w);
            acc = tf32r4(acc);
            *(float4*)(Ap + (tb * 8 + i) * CPAD + c4 * 4) = acc;
            *(float4*)(g_xr + (size_t)(t0 + i) * DM + d) = acc;
        }
    }

    CP_WAIT0();
    __syncthreads();

    const int gid = lane >> 2;
    const int tig = lane & 3;
    const int grp = lane >> 3;
    const int lr  = lane & 7;
    uint32_t aoffb[2];
#pragma unroll
    for (int mt = 0; mt < 2; mt++)
        aoffb[mt] = (uint32_t)(((warp_m * 32 + mt * 16 + (grp & 1) * 8 + lr) * CPAD
                                + (grp >> 1) * 4) * 4);
    uint32_t boff[3];
#pragma unroll
    for (int j = 0; j < 3; j++)
        boff[j] = (uint32_t)(((warp_n * 48 + (2 * j + (grp >> 1)) * 8 + lr) * PADS
                              + (grp & 1) * 4) * 4);

    float acc[2][6][4];
#pragma unroll
    for (int mt = 0; mt < 2; mt++)
#pragma unroll
        for (int nt = 0; nt < 6; nt++)
#pragma unroll
            for (int i = 0; i < 4; i++) acc[mt][nt][i] = 0.f;

#pragma unroll
    for (int t = 0; t < 4; t++) {
        const uint32_t bbase = sbB + (uint32_t)(t * ST_B96 * 4);
#pragma unroll
        for (int k0 = 0; k0 < 4; k0++) {
            uint32_t af[2][4];
#pragma unroll
            for (int mt = 0; mt < 2; mt++)
                ldsm4(af[mt][0], af[mt][1], af[mt][2], af[mt][3],
                      sbA + aoffb[mt] + (t * 32 + k0 * 8) * 4);
#pragma unroll
            for (int j = 0; j < 3; j++) {
                uint32_t b0, b1, b2, b3;
                ldsm4(b0, b1, b2, b3, bbase + boff[j] + k0 * 32);
#pragma unroll
                for (int mt = 0; mt < 2; mt++) {
                    mma_tf32(acc[mt][2 * j + 0], af[mt], b0, b1);
                    mma_tf32(acc[mt][2 * j + 1], af[mt], b2, b3);
                }
            }
        }
    }

    // ---- epilogue: accumulate into g_bcd via red.global ----
#pragma unroll
    for (int mt = 0; mt < 2; mt++) {
#pragma unroll
        for (int nt = 0; nt < 6; nt++) {
            int r0 = bm + warp_m * 32 + mt * 16 + gid;
            int cN = warp_n * 48 + nt * 8 + 2 * tig;
            atomicAdd(&g_bcd[(size_t)r0 * 96 + cN],       acc[mt][nt][0]);
            atomicAdd(&g_bcd[(size_t)r0 * 96 + cN + 1],   acc[mt][nt][1]);
            atomicAdd(&g_bcd[(size_t)(r0 + 8) * 96 + cN],     acc[mt][nt][2]);
            atomicAdd(&g_bcd[(size_t)(r0 + 8) * 96 + cN + 1], acc[mt][nt][3]);
        }
    }
}

// ---------------- prep: pack W_B/W_C/W_D1 (tf32-rounded), zero g_bcd ---------
__global__ void prep_operands(
    const float4* __restrict__ wb, const float4* __restrict__ wc,
    const float4* __restrict__ wd1)
{
    const int n4 = 16 * DM / 4;
    const int n5 = 16 * DM / 4;
    const int n6 = 64 * DM / 4;
    const int n7 = TOK * 96 / 4;
    int i = blockIdx.x * 256 + threadIdx.x;
    if (i < n4) { ((float4*)g_wbcd)[i] = tf32r4(wb[i]); return; }
    i -= n4;
    if (i < n5) { ((float4*)g_wbcd)[16 * DM / 4 + i] = tf32r4(wc[i]); return; }
    i -= n5;
    if (i < n6) { ((float4*)g_wbcd)[32 * DM / 4 + i] = tf32r4(wd1[i]); return; }
    i -= n6;
    if (i < n7) ((float4*)g_bcd)[i] = make_float4(0.f, 0.f, 0.f, 0.f);
}

// ---------------- SSM scan, phase 1: per-chunk local scan --------------------
__global__ __launch_bounds__(128) void scan_phase1(const float* __restrict__ Avec)
{
    __shared__ float Bsm[CHUNK * 16];
    int d = blockIdx.x * 128 + threadIdx.x;
    int c = blockIdx.y;
    int b = blockIdx.z;
    int base_tok = b * LL + c * CHUNK;

    for (int i = threadIdx.x; i < CHUNK * 16; i += 128) {
        int l = i >> 4, s = i & 15;
        Bsm[i] = g_bcd[(size_t)(base_tok + l) * 96 + s];
    }
    __syncthreads();

    float E[16];
#pragma unroll
    for (int s = 0; s < 16; s++) E[s] = __expf(-Avec[d * 16 + s]);
    float h[16];
#pragma unroll
    for (int s = 0; s < 16; s++) h[s] = 0.f;
    float pd = 1.f;

    for (int l = 0; l < CHUNK; l++) {
        int tok = base_tok + l;
        float dl = g_delta[(size_t)tok * DM + d];
        float xv = g_xr[(size_t)tok * DM + d];
        float dx = dl * xv;
        pd *= dl;
#pragma unroll
        for (int s = 0; s < 16; s++)
            h[s] = E[s] * dl * h[s] + Bsm[l * 16 + s] * dx;
    }
    int cb = b * NCH + c;
    g_pd[(size_t)cb * DM + d] = pd;
#pragma unroll
    for (int s = 0; s < 16; s++)
        g_hend[((size_t)cb * 16 + s) * DM + d] = h[s];
}

// ---------------- SSM scan, phase 2: sequential chunk combine ----------------
__global__ __launch_bounds__(256) void scan_phase2(const float* __restrict__ Avec)
{
    int gid = blockIdx.x * 256 + threadIdx.x;
    if (gid >= BBATCH * DM) return;
    int b = gid >> 10;
    int d = gid & (DM - 1);

    float EC[16];
#pragma unroll
    for (int s = 0; s < 16; s++) EC[s] = __expf(-(float)CHUNK * Avec[d * 16 + s]);
    float carry[16];
#pragma unroll
    for (int s = 0; s < 16; s++) carry[s] = 0.f;

    for (int c = 0; c < NCH; c++) {
        int cb = b * NCH + c;
        float pd = g_pd[(size_t)cb * DM + d];
#pragma unroll
        for (int s = 0; s < 16; s++) {
            g_hinit[((size_t)cb * 16 + s) * DM + d] = carry[s];
            carry[s] = EC[s] * pd * carry[s] + g_hend[((size_t)cb * 16 + s) * DM + d];
        }
    }
}

// ---------------- SSM scan, phase 3: replay w/ carry, fused gate+D -----------
__global__ __launch_bounds__(128) void scan_phase3(const float* __restrict__ Avec,
                                                   const float* __restrict__ Dvec)
{
    __shared__ float Bsm[CHUNK * 16];
    __shared__ float Csm[CHUNK * 16];
    int d = blockIdx.x * 128 + threadIdx.x;
    int c = blockIdx.y;
    int b = blockIdx.z;
    int base_tok = b * LL + c * CHUNK;
    int cb = b * NCH + c;

    for (int i = threadIdx.x; i < CHUNK * 16; i += 128) {
        int l = i >> 4, s = i & 15;
        Bsm[i] = g_bcd[(size_t)(base_tok + l) * 96 + s];
        Csm[i] = g_bcd[(size_t)(base_tok + l) * 96 + 16 + s];
    }
    __syncthreads();

    float E[16];
#pragma unroll
    for (int s = 0; s < 16; s++) E[s] = __expf(-Avec[d * 16 + s]);
    float h[16];
#pragma unroll
    for (int s = 0; s < 16; s++)
        h[s] = g_hinit[((size_t)cb * 16 + s) * DM + d];
    float Dd = Dvec[d];

    for (int l = 0; l < CHUNK; l++) {
        int tok = base_tok + l;
        float dl = g_delta[(size_t)tok * DM + d];
        float xv = g_xr[(size_t)tok * DM + d];
        float bg = g_ab[(size_t)tok * (2 * DM) + DM + d];
        float dx = dl * xv;
#pragma unroll
        for (int s = 0; s < 16; s++)
            h[s] = E[s] * dl * h[s] + Bsm[l * 16 + s] * dx;

        float y0 = 0.f, y1 = 0.f, y2 = 0.f, y3 = 0.f;
#pragma unroll
        for (int s = 0; s < 16; s += 4) {
            y0 += h[s + 0] * Csm[l * 16 + s + 0];
            y1 += h[s + 1] * Csm[l * 16 + s + 1];
            y2 += h[s + 2] * Csm[l * 16 + s + 2];
            y3 += h[s + 3] * Csm[l * 16 + s + 3];
        }
        float y = (y0 + y1) + (y2 + y3);
        g_obuf[(size_t)tok * DM + d] = (y + Dd * xv) * silu_f(bg);
    }
}

// ---------------- launch ------------------------------------------------------
#define SMEM_B128 ((BMT + 128) * PADS * 4 * 2)
#define SMEM_B64  ((BMT + 64) * PADS * 4 * 2)

extern "C" void kernel_launch(void* const* d_in, const int* in_sizes, int n_in,
                              void* d_out, int out_size)
{
    const float* seq    = (const float*)d_in[0];
    const float* W_in   = (const float*)d_in[1];
    const float* W_out  = (const float*)d_in[2];
    const float* W_B    = (const float*)d_in[3];
    const float* W_C    = (const float*)d_in[4];
    const float* W_D1   = (const float*)d_in[5];
    const float* W_D2   = (const float*)d_in[6];
    const float* conv_w = (const float*)d_in[7];
    const float* conv_b = (const float*)d_in[8];
    const float* Avec   = (const float*)d_in[9];
    const float* Dvec   = (const float*)d_in[10];
    float* out = (float*)d_out;

    float *ab, *bcd, *delta, *obuf;
    cudaGetSymbolAddress((void**)&ab,    g_ab);
    cudaGetSymbolAddress((void**)&bcd,   g_bcd);
    cudaGetSymbolAddress((void**)&delta, g_delta);
    cudaGetSymbolAddress((void**)&obuf,  g_obuf);

    cudaFuncSetAttribute(gemm_mma<128>, cudaFuncAttributeMaxDynamicSharedMemorySize, SMEM_B128);
    cudaFuncSetAttribute(gemm_mma<64>,  cudaFuncAttributeMaxDynamicSharedMemorySize, SMEM_B64);
    cudaFuncSetAttribute(gemm_bcd_conv, cudaFuncAttributeMaxDynamicSharedMemorySize, SMEM_BCDCONV);

    // 0) prep: pack wbcd (rounded), zero g_bcd accumulator (small)
    const int ntot = 16 * DM / 4 + 16 * DM / 4 + 64 * DM / 4 + TOK * 96 / 4;
    prep_operands<<<(ntot + 255) / 256, 256>>>(
        (const float4*)W_B, (const float4*)W_C, (const float4*)W_D1);

    // 1) ab = seq @ W_in^T   (2048 x 2048 x 512) — raw inputs, fragment cvt
    gemm_mma<128><<<dim3((2 * DM) / 128, TOK / BMT, 1), 256, SMEM_B128>>>(
        seq, DIN, W_in, DIN, ab, 2 * DM, 2 * DM, DIN / BKT, 0, 0, 0, nullptr);

    // 2) fused conv+SiLU + bcd GEMM (split-K=8, atomic accumulate into g_bcd)
    gemm_bcd_conv<<<dim3(1, TOK / 128, KSPLIT_BCD), 256, SMEM_BCDCONV>>>(conv_w, conv_b);

    // 3) delta = softplus(D + xd1 @ W_D2^T)  (2048 x 1024 x 64), BNT=64 -> 256 CTAs
    gemm_mma<64><<<dim3(DM / 64, TOK / BMT, 1), 256, SMEM_B64>>>(
        bcd + 32, 96, W_D2, DD, delta, DM, DM, DD / BKT, 0, 0, 1, Dvec);

    // 4-6) chunked scan (CHUNK=32)
    scan_phase1<<<dim3(DM / 128, NCH, BBATCH), 128>>>(Avec);
    scan_phase2<<<dim3((BBATCH * DM + 255) / 256), 256>>>(Avec);
    scan_phase3<<<dim3(DM / 128, NCH, BBATCH), 128>>>(Avec, Dvec);

    // 7) out = obuf @ W_out^T  (2048 x 512 x 1024)
    gemm_mma<64><<<dim3(DIN / 64, TOK / BMT, 1), 256, SMEM_B64>>>(
        obuf, DM, W_out, DM, out, DIN, DIN, DM / BKT, 0, 0, 0, nullptr);
}

// round 15
// speedup vs baseline: 1.0755x; 1.0755x over previous
#include <cuda_runtime.h>
#include <math.h>
#include <cstdint>

// ---------------- problem constants ------------------------------------------
#define BBATCH 2
#define LL 1024
#define DIN 512
#define DM 1024
#define DS 16
#define DD 64
#define KERW 4
#define TOK (BBATCH * LL)      // 2048
#define CHUNK 32
#define NCH (LL / CHUNK)       // 32
#define KSPLIT_BCD 8

// ---------------- scratch (static device globals) ----------------------------
__device__ __align__(16) float g_ab[TOK * 2 * DM];
__device__ __align__(16) float g_xr[TOK * DM];       // tf32-rounded conv output
__device__ __align__(16) float g_bcd[TOK * 96];      // atomically accumulated
__device__ __align__(16) float g_delta[TOK * DM];
__device__ __align__(16) float g_wbcd[96 * DM];
__device__ __align__(16) float g_hend[BBATCH * NCH * DS * DM];
__device__ __align__(16) float g_pd[BBATCH * NCH * DM];
__device__ __align__(16) float g_hinit[BBATCH * NCH * DS * DM];
__device__ __align__(16) float g_obuf[TOK * DM];
// tf32-rounded copies of GEMM operands
__device__ __align__(16) float g_seq_r[TOK * DIN];
__device__ __align__(16) float g_win_r[2 * DM * DIN];
__device__ __align__(16) float g_wout_r[DIN * DM];
__device__ __align__(16) float g_wd2_r[DM * DD];

// ---------------- small PTX helpers ------------------------------------------
__device__ __forceinline__ uint32_t smem_u32(const void* p) {
    uint32_t a;
    asm("{ .reg .u64 t; cvta.to.shared.u64 t, %1; cvt.u32.u64 %0, t; }" : "=r"(a) : "l"(p));
    return a;
}
__device__ __forceinline__ float tf32r(float x) {
    uint32_t o;
    asm("cvt.rna.tf32.f32 %0, %1;" : "=r"(o) : "f"(x));
    return __uint_as_float(o);
}
__device__ __forceinline__ float4 tf32r4(float4 v) {
    return make_float4(tf32r(v.x), tf32r(v.y), tf32r(v.z), tf32r(v.w));
}
__device__ __forceinline__ void cp16(uint32_t dst, const void* src, int sz) {
    asm volatile("cp.async.ca.shared.global [%0], [%1], 16, %2;"
                 :: "r"(dst), "l"(src), "r"(sz) : "memory");
}
#define CP_COMMIT() asm volatile("cp.async.commit_group;" ::: "memory")
#define CP_WAIT0()  asm volatile("cp.async.wait_group 0;" ::: "memory")

// fast softplus / silu (MUFU-based intrinsics; rel err ~1e-7, far under budget)
__device__ __forceinline__ float softplus_f(float z) {
    return fmaxf(z, 0.f) + __logf(1.f + __expf(-fabsf(z)));
}
__device__ __forceinline__ float silu_f(float x) {
    return __fdividef(x, 1.f + __expf(-x));
}

__device__ __forceinline__ void mma_tf32(float* c, const uint32_t* a, uint32_t b0, uint32_t b1) {
    asm volatile(
        "mma.sync.aligned.m16n8k8.row.col.f32.tf32.tf32.f32 "
        "{%0,%1,%2,%3}, {%4,%5,%6,%7}, {%8,%9}, {%0,%1,%2,%3};"
        : "+f"(c[0]), "+f"(c[1]), "+f"(c[2]), "+f"(c[3])
        : "r"(a[0]), "r"(a[1]), "r"(a[2]), "r"(a[3]), "r"(b0), "r"(b1));
}
__device__ __forceinline__ void ldsm4(uint32_t& r0, uint32_t& r1, uint32_t& r2, uint32_t& r3,
                                      uint32_t addr) {
    asm volatile("ldmatrix.sync.aligned.m8n8.x4.shared.b16 {%0,%1,%2,%3}, [%4];"
                 : "=r"(r0), "=r"(r1), "=r"(r2), "=r"(r3) : "r"(addr));
}

// ---------------- generic tf32 GEMM:  C[M,N] = A[M,K] * W[N,K]^T -------------
// Pre-rounded tf32 operands; cvt-free ldmatrix mainloop.
#define BMT 128
#define BKT 32
#define PADS 36

// mode: 0 = plain store, 1 = softplus(aux[col] + acc)
template <int BNT>
__global__ __launch_bounds__(256) void gemm_mma(
    const float* __restrict__ A, int lda,
    const float* __restrict__ W, int ldw,
    float* __restrict__ C, int ldc,
    int Nvalid, int T, int kstride, long cstride,
    int mode, const float* __restrict__ aux)
{
    constexpr int NT = BNT / 16;
    constexpr int stA = BMT * PADS;
    constexpr int stB = BNT * PADS;

    extern __shared__ float smem[];
    float* As = smem;
    float* Bs = smem + 2 * stA;
    const uint32_t sbA = smem_u32(As);
    const uint32_t sbB = smem_u32(Bs);

    const int tid = threadIdx.x;
    const int lane = tid & 31;
    const int wid = tid >> 5;
    const int warp_m = wid & 3;
    const int warp_n = wid >> 2;
    const int bm = blockIdx.y * BMT;
    const int bn = blockIdx.x * BNT;
    const int koff = blockIdx.z * kstride;
    C += (long)blockIdx.z * cstride;

    const int gid = lane >> 2;
    const int tig = lane & 3;
    const int grp = lane >> 3;
    const int lr  = lane & 7;

    uint32_t aoff[2];
#pragma unroll
    for (int mt = 0; mt < 2; mt++)
        aoff[mt] = (uint32_t)(((warp_m * 32 + mt * 16 + (grp & 1) * 8 + lr) * PADS
                               + (grp >> 1) * 4) * 4);
    uint32_t boff[NT / 2];
#pragma unroll
    for (int j = 0; j < NT / 2; j++)
        boff[j] = (uint32_t)(((warp_n * (BNT / 2) + (2 * j + (grp >> 1)) * 8 + lr) * PADS
                              + (grp & 1) * 4) * 4);

    float acc[2][NT][4];
#pragma unroll
    for (int mt = 0; mt < 2; mt++)
#pragma unroll
        for (int nt = 0; nt < NT; nt++)
#pragma unroll
            for (int i = 0; i < 4; i++) acc[mt][nt][i] = 0.f;

    auto load_tiles = [&](int st, int t) {
        const int kc = koff + t * BKT;
#pragma unroll
        for (int j = 0; j < (BMT * 8) / 256; j++) {
            int idx = tid + j * 256;
            int row = idx >> 3, c4 = idx & 7;
            cp16(sbA + (uint32_t)(st * stA + row * PADS + c4 * 4) * 4,
                 A + (size_t)(bm + row) * lda + kc + c4 * 4, 16);
        }
#pragma unroll
        for (int j = 0; j < (BNT * 8 + 255) / 256; j++) {
            int idx = tid + j * 256;
            if (idx < BNT * 8) {
                int row = idx >> 3, c4 = idx & 7;
                bool v = (bn + row) < Nvalid;
                cp16(sbB + (uint32_t)(st * stB + row * PADS + c4 * 4) * 4,
                     W + (size_t)(v ? bn + row : 0) * ldw + kc + c4 * 4, v ? 16 : 0);
            }
        }
    };

    load_tiles(0, 0);
    CP_COMMIT();

    for (int t = 0; t < T; t++) {
        CP_WAIT0();
        __syncthreads();
        if (t + 1 < T) { load_tiles((t + 1) & 1, t + 1); CP_COMMIT(); }

        const uint32_t abase = sbA + (uint32_t)((t & 1) * stA * 4);
        const uint32_t bbase = sbB + (uint32_t)((t & 1) * stB * 4);
#pragma unroll
        for (int k0 = 0; k0 < 4; k0++) {
            uint32_t af[2][4];
#pragma unroll
            for (int mt = 0; mt < 2; mt++)
                ldsm4(af[mt][0], af[mt][1], af[mt][2], af[mt][3],
                      abase + aoff[mt] + k0 * 32);
#pragma unroll
            for (int j = 0; j < NT / 2; j++) {
                uint32_t b0, b1, b2, b3;
                ldsm4(b0, b1, b2, b3, bbase + boff[j] + k0 * 32);
#pragma unroll
                for (int mt = 0; mt < 2; mt++) {
                    mma_tf32(acc[mt][2 * j + 0], af[mt], b0, b1);
                    mma_tf32(acc[mt][2 * j + 1], af[mt], b2, b3);
                }
            }
        }
    }

    // ---- epilogue ----
#pragma unroll
    for (int mt = 0; mt < 2; mt++) {
#pragma unroll
        for (int nt = 0; nt < NT; nt++) {
            int r0 = bm + warp_m * 32 + mt * 16 + gid;
            int cN = bn + warp_n * (BNT / 2) + nt * 8 + 2 * tig;
            if (cN < Nvalid) {
                float v0 = acc[mt][nt][0], v1 = acc[mt][nt][1];
                float v2 = acc[mt][nt][2], v3 = acc[mt][nt][3];
                if (mode == 1) {
                    float d0 = aux[cN], d1 = aux[cN + 1];
                    v0 = softplus_f(d0 + v0);
                    v1 = softplus_f(d1 + v1);
                    v2 = softplus_f(d0 + v2);
                    v3 = softplus_f(d1 + v3);
                }
                *(float2*)&C[(size_t)r0 * ldc + cN] = make_float2(v0, v1);
                *(float2*)&C[(size_t)(r0 + 8) * ldc + cN] = make_float2(v2, v3);
            }
        }
    }
}

// ---------------- fused conv+SiLU + bcd GEMM (N=96, T=4, split-K over d) -----
#define CPAD 132
#define ST_B96 (96 * PADS)
#define SMEM_BCDCONV ((128 * CPAD + 4 * ST_B96) * 4)

__global__ __launch_bounds__(256) void gemm_bcd_conv(
    const float* __restrict__ cw, const float* __restrict__ cb)
{
    extern __shared__ float smem[];
    float* Ap = smem;                        // [128][CPAD]
    float* Bs = smem + 128 * CPAD;           // [4][96][PADS]
    const uint32_t sbA = smem_u32(Ap);
    const uint32_t sbB = smem_u32(Bs);

    const int tid = threadIdx.x;
    const int lane = tid & 31;
    const int wid = tid >> 5;
    const int warp_m = wid & 3;
    const int warp_n = wid >> 2;
    const int bm = blockIdx.y * 128;
    const int koff = blockIdx.z * (DM / KSPLIT_BCD);

    // ---- prologue: prefetch ALL 4 B k-tiles ----
#pragma unroll
    for (int t = 0; t < 4; t++) {
        const int kc = koff + t * BKT;
#pragma unroll
        for (int j = 0; j < 3; j++) {
            int idx = tid + j * 256;
            if (idx < 96 * 8) {
                int row = idx >> 3, c4 = idx & 7;
                cp16(sbB + (uint32_t)(t * ST_B96 + row * PADS + c4 * 4) * 4,
                     g_wbcd + (size_t)row * DM + kc + c4 * 4, 16);
            }
        }
        CP_COMMIT();
    }

    // ---- conv phase ----
    for (int task = tid; task < 512; task += 256) {
        int c4 = task & 31;
        int tb = task >> 5;
        int t0 = bm + tb * 8;
        int l0 = t0 & (LL - 1);
        int base = t0 - l0;
        int d = koff + c4 * 4;

        float4 cb4 = *(const float4*)(cb + d);
        float4 w0 = *(const float4*)(cw + (d + 0) * KERW);
        float4 w1 = *(const float4*)(cw + (d + 1) * KERW);
        float4 w2 = *(const float4*)(cw + (d + 2) * KERW);
        float4 w3 = *(const float4*)(cw + (d + 3) * KERW);
        float4 wk[KERW];
        wk[0] = make_float4(w0.x, w1.x, w2.x, w3.x);
        wk[1] = make_float4(w0.y, w1.y, w2.y, w3.y);
        wk[2] = make_float4(w0.z, w1.z, w2.z, w3.z);
        wk[3] = make_float4(w0.w, w1.w, w2.w, w3.w);

        float4 win[8 + KERW - 1];
#pragma unroll
        for (int j = 0; j < 8 + KERW - 1; j++) {
            int ll = l0 - (KERW - 1) + j;
            if (ll >= 0)
                win[j] = *(const float4*)(g_ab + (size_t)(base + ll) * (2 * DM) + d);
            else
                win[j] = make_float4(0.f, 0.f, 0.f, 0.f);
        }
#pragma unroll
        for (int i = 0; i < 8; i++) {
            float4 acc = cb4;
#pragma unroll
            for (int k = 0; k < KERW; k++) {
                float4 a = win[i + k];
                acc.x += a.x * wk[k].x; acc.y += a.y * wk[k].y;
                acc.z += a.z * wk[k].z; acc.w += a.w * wk[k].w;
            }
            acc.x = silu_f(acc.x); acc.y = silu_f(acc.y);
            acc.z = silu_f(acc.z); acc.w = silu_f(acc.w);
            acc = tf32r4(acc);
            *(float4*)(Ap + (tb * 8 + i) * CPAD + c4 * 4) = acc;
            *(float4*)(g_xr + (size_t)(t0 + i) * DM + d) = acc;
        }
    }

    CP_WAIT0();
    __syncthreads();

    const int gid = lane >> 2;
    const int tig = lane & 3;
    const int grp = lane >> 3;
    const int lr  = lane & 7;
    uint32_t aoffb[2];
#pragma unroll
    for (int mt = 0; mt < 2; mt++)
        aoffb[mt] = (uint32_t)(((warp_m * 32 + mt * 16 + (grp & 1) * 8 + lr) * CPAD
                                + (grp >> 1) * 4) * 4);
    uint32_t boff[3];
#pragma unroll
    for (int j = 0; j < 3; j++)
        boff[j] = (uint32_t)(((warp_n * 48 + (2 * j + (grp >> 1)) * 8 + lr) * PADS
                              + (grp & 1) * 4) * 4);

    float acc[2][6][4];
#pragma unroll
    for (int mt = 0; mt < 2; mt++)
#pragma unroll
        for (int nt = 0; nt < 6; nt++)
#pragma unroll
            for (int i = 0; i < 4; i++) acc[mt][nt][i] = 0.f;

#pragma unroll
    for (int t = 0; t < 4; t++) {
        const uint32_t bbase = sbB + (uint32_t)(t * ST_B96 * 4);
#pragma unroll
        for (int k0 = 0; k0 < 4; k0++) {
            uint32_t af[2][4];
#pragma unroll
            for (int mt = 0; mt < 2; mt++)
                ldsm4(af[mt][0], af[mt][1], af[mt][2], af[mt][3],
                      sbA + aoffb[mt] + (t * 32 + k0 * 8) * 4);
#pragma unroll
            for (int j = 0; j < 3; j++) {
                uint32_t b0, b1, b2, b3;
                ldsm4(b0, b1, b2, b3, bbase + boff[j] + k0 * 32);
#pragma unroll
                for (int mt = 0; mt < 2; mt++) {
                    mma_tf32(acc[mt][2 * j + 0], af[mt], b0, b1);
                    mma_tf32(acc[mt][2 * j + 1], af[mt], b2, b3);
                }
            }
        }
    }

    // ---- epilogue: accumulate into g_bcd via red.global ----
#pragma unroll
    for (int mt = 0; mt < 2; mt++) {
#pragma unroll
        for (int nt = 0; nt < 6; nt++) {
            int r0 = bm + warp_m * 32 + mt * 16 + gid;
            int cN = warp_n * 48 + nt * 8 + 2 * tig;
            atomicAdd(&g_bcd[(size_t)r0 * 96 + cN],       acc[mt][nt][0]);
            atomicAdd(&g_bcd[(size_t)r0 * 96 + cN + 1],   acc[mt][nt][1]);
            atomicAdd(&g_bcd[(size_t)(r0 + 8) * 96 + cN],     acc[mt][nt][2]);
            atomicAdd(&g_bcd[(size_t)(r0 + 8) * 96 + cN + 1], acc[mt][nt][3]);
        }
    }
}

// ---------------- prep: round operands, pack W_B/W_C/W_D1, zero g_bcd --------
__global__ void prep_operands(
    const float4* __restrict__ seq,  const float4* __restrict__ win,
    const float4* __restrict__ wout, const float4* __restrict__ wd2,
    const float4* __restrict__ wb,   const float4* __restrict__ wc,
    const float4* __restrict__ wd1)
{
    const int n0 = TOK * DIN / 4;
    const int n1 = 2 * DM * DIN / 4;
    const int n2 = DIN * DM / 4;
    const int n3 = DM * DD / 4;
    const int n4 = 16 * DM / 4;
    const int n5 = 16 * DM / 4;
    const int n6 = 64 * DM / 4;
    const int n7 = TOK * 96 / 4;
    int i = blockIdx.x * 256 + threadIdx.x;
    if (i < n0) { ((float4*)g_seq_r)[i] = tf32r4(seq[i]); return; }
    i -= n0;
    if (i < n1) { ((float4*)g_win_r)[i] = tf32r4(win[i]); return; }
    i -= n1;
    if (i < n2) { ((float4*)g_wout_r)[i] = tf32r4(wout[i]); return; }
    i -= n2;
    if (i < n3) { ((float4*)g_wd2_r)[i] = tf32r4(wd2[i]); return; }
    i -= n3;
    if (i < n4) { ((float4*)g_wbcd)[i] = tf32r4(wb[i]); return; }
    i -= n4;
    if (i < n5) { ((float4*)g_wbcd)[16 * DM / 4 + i] = tf32r4(wc[i]); return; }
    i -= n5;
    if (i < n6) { ((float4*)g_wbcd)[32 * DM / 4 + i] = tf32r4(wd1[i]); return; }
    i -= n6;
    if (i < n7) ((float4*)g_bcd)[i] = make_float4(0.f, 0.f, 0.f, 0.f);
}

// ---------------- SSM scan, phase 1: per-chunk local scan --------------------
__global__ __launch_bounds__(128) void scan_phase1(const float* __restrict__ Avec)
{
    __shared__ float Bsm[CHUNK * 16];
    int d = blockIdx.x * 128 + threadIdx.x;
    int c = blockIdx.y;
    int b = blockIdx.z;
    int base_tok = b * LL + c * CHUNK;

    for (int i = threadIdx.x; i < CHUNK * 16; i += 128) {
        int l = i >> 4, s = i & 15;
        Bsm[i] = g_bcd[(size_t)(base_tok + l) * 96 + s];
    }
    __syncthreads();

    float E[16];
#pragma unroll
    for (int s = 0; s < 16; s++) E[s] = __expf(-Avec[d * 16 + s]);
    float h[16];
#pragma unroll
    for (int s = 0; s < 16; s++) h[s] = 0.f;
    float pd = 1.f;

    for (int l = 0; l < CHUNK; l++) {
        int tok = base_tok + l;
        float dl = g_delta[(size_t)tok * DM + d];
        float xv = g_xr[(size_t)tok * DM + d];
        float dx = dl * xv;
        pd *= dl;
#pragma unroll
        for (int s = 0; s < 16; s++)
            h[s] = E[s] * dl * h[s] + Bsm[l * 16 + s] * dx;
    }
    int cb = b * NCH + c;
    g_pd[(size_t)cb * DM + d] = pd;
#pragma unroll
    for (int s = 0; s < 16; s++)
        g_hend[((size_t)cb * 16 + s) * DM + d] = h[s];
}

// ---------------- SSM scan, phase 2: sequential chunk combine ----------------
__global__ __launch_bounds__(256) void scan_phase2(const float* __restrict__ Avec)
{
    int gid = blockIdx.x * 256 + threadIdx.x;
    if (gid >= BBATCH * DM) return;
    int b = gid >> 10;
    int d = gid & (DM - 1);

    float EC[16];
#pragma unroll
    for (int s = 0; s < 16; s++) EC[s] = __expf(-(float)CHUNK * Avec[d * 16 + s]);
    float carry[16];
#pragma unroll
    for (int s = 0; s < 16; s++) carry[s] = 0.f;

    for (int c = 0; c < NCH; c++) {
        int cb = b * NCH + c;
        float pd = g_pd[(size_t)cb * DM + d];
#pragma unroll
        for (int s = 0; s < 16; s++) {
            g_hinit[((size_t)cb * 16 + s) * DM + d] = carry[s];
            carry[s] = EC[s] * pd * carry[s] + g_hend[((size_t)cb * 16 + s) * DM + d];
        }
    }
}

// ---------------- SSM scan, phase 3: replay w/ carry, fused gate+D -----------
__global__ __launch_bounds__(128) void scan_phase3(const float* __restrict__ Avec,
                                                   const float* __restrict__ Dvec)
{
    __shared__ float Bsm[CHUNK * 16];
    __shared__ float Csm[CHUNK * 16];
    int d = blockIdx.x * 128 + threadIdx.x;
    int c = blockIdx.y;
    int b = blockIdx.z;
    int base_tok = b * LL + c * CHUNK;
    int cb = b * NCH + c;

    for (int i = threadIdx.x; i < CHUNK * 16; i += 128) {
        int l = i >> 4, s = i & 15;
        Bsm[i] = g_bcd[(size_t)(base_tok + l) * 96 + s];
        Csm[i] = g_bcd[(size_t)(base_tok + l) * 96 + 16 + s];
    }
    __syncthreads();

    float E[16];
#pragma unroll
    for (int s = 0; s < 16; s++) E[s] = __expf(-Avec[d * 16 + s]);
    float h[16];
#pragma unroll
    for (int s = 0; s < 16; s++)
        h[s] = g_hinit[((size_t)cb * 16 + s) * DM + d];
    float Dd = Dvec[d];

    for (int l = 0; l < CHUNK; l++) {
        int tok = base_tok + l;
        float dl = g_delta[(size_t)tok * DM + d];
        float xv = g_xr[(size_t)tok * DM + d];
        float bg = g_ab[(size_t)tok * (2 * DM) + DM + d];
        float dx = dl * xv;
#pragma unroll
        for (int s = 0; s < 16; s++)
            h[s] = E[s] * dl * h[s] + Bsm[l * 16 + s] * dx;

        float y0 = 0.f, y1 = 0.f, y2 = 0.f, y3 = 0.f;
#pragma unroll
        for (int s = 0; s < 16; s += 4) {
            y0 += h[s + 0] * Csm[l * 16 + s + 0];
            y1 += h[s + 1] * Csm[l * 16 + s + 1];
            y2 += h[s + 2] * Csm[l * 16 + s + 2];
            y3 += h[s + 3] * Csm[l * 16 + s + 3];
        }
        float y = (y0 + y1) + (y2 + y3);
        g_obuf[(size_t)tok * DM + d] = tf32r((y + Dd * xv) * silu_f(bg));
    }
}

// ---------------- launch ------------------------------------------------------
#define SMEM_B128 ((BMT + 128) * PADS * 4 * 2)
#define SMEM_B64  ((BMT + 64) * PADS * 4 * 2)

extern "C" void kernel_launch(void* const* d_in, const int* in_sizes, int n_in,
                              void* d_out, int out_size)
{
    const float* seq    = (const float*)d_in[0];
    const float* W_in   = (const float*)d_in[1];
    const float* W_out  = (const float*)d_in[2];
    const float* W_B    = (const float*)d_in[3];
    const float* W_C    = (const float*)d_in[4];
    const float* W_D1   = (const float*)d_in[5];
    const float* W_D2   = (const float*)d_in[6];
    const float* conv_w = (const float*)d_in[7];
    const float* conv_b = (const float*)d_in[8];
    const float* Avec   = (const float*)d_in[9];
    const float* Dvec   = (const float*)d_in[10];
    float* out = (float*)d_out;

    float *ab, *bcd, *delta, *obuf, *seqr, *winr, *woutr, *wd2r;
    cudaGetSymbolAddress((void**)&ab,    g_ab);
    cudaGetSymbolAddress((void**)&bcd,   g_bcd);
    cudaGetSymbolAddress((void**)&delta, g_delta);
    cudaGetSymbolAddress((void**)&obuf,  g_obuf);
    cudaGetSymbolAddress((void**)&seqr,  g_seq_r);
    cudaGetSymbolAddress((void**)&winr,  g_win_r);
    cudaGetSymbolAddress((void**)&woutr, g_wout_r);
    cudaGetSymbolAddress((void**)&wd2r,  g_wd2_r);

    cudaFuncSetAttribute(gemm_mma<128>, cudaFuncAttributeMaxDynamicSharedMemorySize, SMEM_B128);
    cudaFuncSetAttribute(gemm_mma<64>,  cudaFuncAttributeMaxDynamicSharedMemorySize, SMEM_B64);
    cudaFuncSetAttribute(gemm_bcd_conv, cudaFuncAttributeMaxDynamicSharedMemorySize, SMEM_BCDCONV);

    // 0) prep: round operands, pack wbcd, zero g_bcd accumulator
    const int ntot = TOK * DIN / 4 + 2 * DM * DIN / 4 + DIN * DM / 4 + DM * DD / 4
                   + 16 * DM / 4 + 16 * DM / 4 + 64 * DM / 4 + TOK * 96 / 4;
    prep_operands<<<(ntot + 255) / 256, 256>>>(
        (const float4*)seq, (const float4*)W_in, (const float4*)W_out,
        (const float4*)W_D2, (const float4*)W_B, (const float4*)W_C,
        (const float4*)W_D1);

    // 1) ab = seq @ W_in^T   (2048 x 2048 x 512)
    gemm_mma<128><<<dim3((2 * DM) / 128, TOK / BMT, 1), 256, SMEM_B128>>>(
        seqr, DIN, winr, DIN, ab, 2 * DM, 2 * DM, DIN / BKT, 0, 0, 0, nullptr);

    // 2) fused conv+SiLU + bcd GEMM (split-K=8, atomic accumulate into g_bcd)
    gemm_bcd_conv<<<dim3(1, TOK / 128, KSPLIT_BCD), 256, SMEM_BCDCONV>>>(conv_w, conv_b);

    // 3) delta = softplus(D + xd1 @ W_D2^T)  (2048 x 1024 x 64), BNT=64 -> 256 CTAs
    gemm_mma<64><<<dim3(DM / 64, TOK / BMT, 1), 256, SMEM_B64>>>(
        bcd + 32, 96, wd2r, DD, delta, DM, DM, DD / BKT, 0, 0, 1, Dvec);

    // 4-6) chunked scan (CHUNK=32)
    scan_phase1<<<dim3(DM / 128, NCH, BBATCH), 128>>>(Avec);
    scan_phase2<<<dim3((BBATCH * DM + 255) / 256), 256>>>(Avec);
    scan_phase3<<<dim3(DM / 128, NCH, BBATCH), 128>>>(Avec, Dvec);

    // 7) out = obuf @ W_out^T  (2048 x 512 x 1024)
    gemm_mma<64><<<dim3(DIN / 64, TOK / BMT, 1), 256, SMEM_B64>>>(
        obuf, DM, woutr, DM, out, DIN, DIN, DM / BKT, 0, 0, 0, nullptr);
}

// round 16
// speedup vs baseline: 1.0883x; 1.0119x over previous
#include <cuda_runtime.h>
#include <math.h>
#include <cstdint>

// ---------------- problem constants ------------------------------------------
#define BBATCH 2
#define LL 1024
#define DIN 512
#define DM 1024
#define DS 16
#define DD 64
#define KERW 4
#define TOK (BBATCH * LL)      // 2048
#define CHUNK 32
#define NCH (LL / CHUNK)       // 32
#define KSPLIT_BCD 8
#define SCAN_CTAS ((DM / 128) * NCH * BBATCH)   // 512
#define P2_CTAS   ((DM / 128) * BBATCH)         // 16

// ---------------- scratch (static device globals) ----------------------------
__device__ __align__(16) float g_ab[TOK * 2 * DM];
__device__ __align__(16) float g_xr[TOK * DM];       // tf32-rounded conv output
__device__ __align__(16) float g_bcd[TOK * 96];      // atomically accumulated
__device__ __align__(16) float g_delta[TOK * DM];
__device__ __align__(16) float g_wbcd[96 * DM];
__device__ __align__(16) float g_hend[BBATCH * NCH * DS * DM];
__device__ __align__(16) float g_pd[BBATCH * NCH * DM];
__device__ __align__(16) float g_hinit[BBATCH * NCH * DS * DM];
__device__ __align__(16) float g_obuf[TOK * DM];
__device__ int g_sync1;
__device__ int g_sync2;
// tf32-rounded copies of GEMM operands
__device__ __align__(16) float g_seq_r[TOK * DIN];
__device__ __align__(16) float g_win_r[2 * DM * DIN];
__device__ __align__(16) float g_wout_r[DIN * DM];
__device__ __align__(16) float g_wd2_r[DM * DD];

// ---------------- small PTX helpers ------------------------------------------
__device__ __forceinline__ uint32_t smem_u32(const void* p) {
    uint32_t a;
    asm("{ .reg .u64 t; cvta.to.shared.u64 t, %1; cvt.u32.u64 %0, t; }" : "=r"(a) : "l"(p));
    return a;
}
__device__ __forceinline__ float tf32r(float x) {
    uint32_t o;
    asm("cvt.rna.tf32.f32 %0, %1;" : "=r"(o) : "f"(x));
    return __uint_as_float(o);
}
__device__ __forceinline__ float4 tf32r4(float4 v) {
    return make_float4(tf32r(v.x), tf32r(v.y), tf32r(v.z), tf32r(v.w));
}
__device__ __forceinline__ void cp16(uint32_t dst, const void* src, int sz) {
    asm volatile("cp.async.ca.shared.global [%0], [%1], 16, %2;"
                 :: "r"(dst), "l"(src), "r"(sz) : "memory");
}
#define CP_COMMIT() asm volatile("cp.async.commit_group;" ::: "memory")
#define CP_WAIT0()  asm volatile("cp.async.wait_group 0;" ::: "memory")

// fast softplus / silu (MUFU-based intrinsics; rel err ~1e-7, far under budget)
__device__ __forceinline__ float softplus_f(float z) {
    return fmaxf(z, 0.f) + __logf(1.f + __expf(-fabsf(z)));
}
__device__ __forceinline__ float silu_f(float x) {
    return __fdividef(x, 1.f + __expf(-x));
}

__device__ __forceinline__ void mma_tf32(float* c, const uint32_t* a, uint32_t b0, uint32_t b1) {
    asm volatile(
        "mma.sync.aligned.m16n8k8.row.col.f32.tf32.tf32.f32 "
        "{%0,%1,%2,%3}, {%4,%5,%6,%7}, {%8,%9}, {%0,%1,%2,%3};"
        : "+f"(c[0]), "+f"(c[1]), "+f"(c[2]), "+f"(c[3])
        : "r"(a[0]), "r"(a[1]), "r"(a[2]), "r"(a[3]), "r"(b0), "r"(b1));
}
__device__ __forceinline__ void ldsm4(uint32_t& r0, uint32_t& r1, uint32_t& r2, uint32_t& r3,
                                      uint32_t addr) {
    asm volatile("ldmatrix.sync.aligned.m8n8.x4.shared.b16 {%0,%1,%2,%3}, [%4];"
                 : "=r"(r0), "=r"(r1), "=r"(r2), "=r"(r3) : "r"(addr));
}

// ---------------- generic tf32 GEMM:  C[M,N] = A[M,K] * W[N,K]^T -------------
// Pre-rounded tf32 operands; cvt-free ldmatrix mainloop.
#define BMT 128
#define BKT 32
#define PADS 36

// mode: 0 = plain store, 1 = softplus(aux[col] + acc)
template <int BNT>
__global__ __launch_bounds__(256) void gemm_mma(
    const float* __restrict__ A, int lda,
    const float* __restrict__ W, int ldw,
    float* __restrict__ C, int ldc,
    int Nvalid, int T, int kstride, long cstride,
    int mode, const float* __restrict__ aux)
{
    constexpr int NT = BNT / 16;
    constexpr int stA = BMT * PADS;
    constexpr int stB = BNT * PADS;

    extern __shared__ float smem[];
    float* As = smem;
    float* Bs = smem + 2 * stA;
    const uint32_t sbA = smem_u32(As);
    const uint32_t sbB = smem_u32(Bs);

    const int tid = threadIdx.x;
    const int lane = tid & 31;
    const int wid = tid >> 5;
    const int warp_m = wid & 3;
    const int warp_n = wid >> 2;
    const int bm = blockIdx.y * BMT;
    const int bn = blockIdx.x * BNT;
    const int koff = blockIdx.z * kstride;
    C += (long)blockIdx.z * cstride;

    const int gid = lane >> 2;
    const int tig = lane & 3;
    const int grp = lane >> 3;
    const int lr  = lane & 7;

    uint32_t aoff[2];
#pragma unroll
    for (int mt = 0; mt < 2; mt++)
        aoff[mt] = (uint32_t)(((warp_m * 32 + mt * 16 + (grp & 1) * 8 + lr) * PADS
                               + (grp >> 1) * 4) * 4);
    uint32_t boff[NT / 2];
#pragma unroll
    for (int j = 0; j < NT / 2; j++)
        boff[j] = (uint32_t)(((warp_n * (BNT / 2) + (2 * j + (grp >> 1)) * 8 + lr) * PADS
                              + (grp & 1) * 4) * 4);

    float acc[2][NT][4];
#pragma unroll
    for (int mt = 0; mt < 2; mt++)
#pragma unroll
        for (int nt = 0; nt < NT; nt++)
#pragma unroll
            for (int i = 0; i < 4; i++) acc[mt][nt][i] = 0.f;

    auto load_tiles = [&](int st, int t) {
        const int kc = koff + t * BKT;
#pragma unroll
        for (int j = 0; j < (BMT * 8) / 256; j++) {
            int idx = tid + j * 256;
            int row = idx >> 3, c4 = idx & 7;
            cp16(sbA + (uint32_t)(st * stA + row * PADS + c4 * 4) * 4,
                 A + (size_t)(bm + row) * lda + kc + c4 * 4, 16);
        }
#pragma unroll
        for (int j = 0; j < (BNT * 8 + 255) / 256; j++) {
            int idx = tid + j * 256;
            if (idx < BNT * 8) {
                int row = idx >> 3, c4 = idx & 7;
                bool v = (bn + row) < Nvalid;
                cp16(sbB + (uint32_t)(st * stB + row * PADS + c4 * 4) * 4,
                     W + (size_t)(v ? bn + row : 0) * ldw + kc + c4 * 4, v ? 16 : 0);
            }
        }
    };

    load_tiles(0, 0);
    CP_COMMIT();

    for (int t = 0; t < T; t++) {
        CP_WAIT0();
        __syncthreads();
        if (t + 1 < T) { load_tiles((t + 1) & 1, t + 1); CP_COMMIT(); }

        const uint32_t abase = sbA + (uint32_t)((t & 1) * stA * 4);
        const uint32_t bbase = sbB + (uint32_t)((t & 1) * stB * 4);
#pragma unroll
        for (int k0 = 0; k0 < 4; k0++) {
            uint32_t af[2][4];
#pragma unroll
            for (int mt = 0; mt < 2; mt++)
                ldsm4(af[mt][0], af[mt][1], af[mt][2], af[mt][3],
                      abase + aoff[mt] + k0 * 32);
#pragma unroll
            for (int j = 0; j < NT / 2; j++) {
                uint32_t b0, b1, b2, b3;
                ldsm4(b0, b1, b2, b3, bbase + boff[j] + k0 * 32);
#pragma unroll
                for (int mt = 0; mt < 2; mt++) {
                    mma_tf32(acc[mt][2 * j + 0], af[mt], b0, b1);
                    mma_tf32(acc[mt][2 * j + 1], af[mt], b2, b3);
                }
            }
        }
    }

    // ---- epilogue ----
#pragma unroll
    for (int mt = 0; mt < 2; mt++) {
#pragma unroll
        for (int nt = 0; nt < NT; nt++) {
            int r0 = bm + warp_m * 32 + mt * 16 + gid;
            int cN = bn + warp_n * (BNT / 2) + nt * 8 + 2 * tig;
            if (cN < Nvalid) {
                float v0 = acc[mt][nt][0], v1 = acc[mt][nt][1];
                float v2 = acc[mt][nt][2], v3 = acc[mt][nt][3];
                if (mode == 1) {
                    float d0 = aux[cN], d1 = aux[cN + 1];
                    v0 = softplus_f(d0 + v0);
                    v1 = softplus_f(d1 + v1);
                    v2 = softplus_f(d0 + v2);
                    v3 = softplus_f(d1 + v3);
                }
                *(float2*)&C[(size_t)r0 * ldc + cN] = make_float2(v0, v1);
                *(float2*)&C[(size_t)(r0 + 8) * ldc + cN] = make_float2(v2, v3);
            }
        }
    }
}

// ---------------- fused conv+SiLU + bcd GEMM (N=96, T=4, split-K over d) -----
#define CPAD 132
#define ST_B96 (96 * PADS)
#define SMEM_BCDCONV ((128 * CPAD + 4 * ST_B96) * 4)

__global__ __launch_bounds__(256) void gemm_bcd_conv(
    const float* __restrict__ cw, const float* __restrict__ cb)
{
    extern __shared__ float smem[];
    float* Ap = smem;                        // [128][CPAD]
    float* Bs = smem + 128 * CPAD;           // [4][96][PADS]
    const uint32_t sbA = smem_u32(Ap);
    const uint32_t sbB = smem_u32(Bs);

    const int tid = threadIdx.x;
    const int lane = tid & 31;
    const int wid = tid >> 5;
    const int warp_m = wid & 3;
    const int warp_n = wid >> 2;
    const int bm = blockIdx.y * 128;
    const int koff = blockIdx.z * (DM / KSPLIT_BCD);

    // ---- prologue: prefetch ALL 4 B k-tiles ----
#pragma unroll
    for (int t = 0; t < 4; t++) {
        const int kc = koff + t * BKT;
#pragma unroll
        for (int j = 0; j < 3; j++) {
            int idx = tid + j * 256;
            if (idx < 96 * 8) {
                int row = idx >> 3, c4 = idx & 7;
                cp16(sbB + (uint32_t)(t * ST_B96 + row * PADS + c4 * 4) * 4,
                     g_wbcd + (size_t)row * DM + kc + c4 * 4, 16);
            }
        }
        CP_COMMIT();
    }

    // ---- conv phase ----
    for (int task = tid; task < 512; task += 256) {
        int c4 = task & 31;
        int tb = task >> 5;
        int t0 = bm + tb * 8;
        int l0 = t0 & (LL - 1);
        int base = t0 - l0;
        int d = koff + c4 * 4;

        float4 cb4 = *(const float4*)(cb + d);
        float4 w0 = *(const float4*)(cw + (d + 0) * KERW);
        float4 w1 = *(const float4*)(cw + (d + 1) * KERW);
        float4 w2 = *(const float4*)(cw + (d + 2) * KERW);
        float4 w3 = *(const float4*)(cw + (d + 3) * KERW);
        float4 wk[KERW];
        wk[0] = make_float4(w0.x, w1.x, w2.x, w3.x);
        wk[1] = make_float4(w0.y, w1.y, w2.y, w3.y);
        wk[2] = make_float4(w0.z, w1.z, w2.z, w3.z);
        wk[3] = make_float4(w0.w, w1.w, w2.w, w3.w);

        float4 win[8 + KERW - 1];
#pragma unroll
        for (int j = 0; j < 8 + KERW - 1; j++) {
            int ll = l0 - (KERW - 1) + j;
            if (ll >= 0)
                win[j] = *(const float4*)(g_ab + (size_t)(base + ll) * (2 * DM) + d);
            else
                win[j] = make_float4(0.f, 0.f, 0.f, 0.f);
        }
#pragma unroll
        for (int i = 0; i < 8; i++) {
            float4 acc = cb4;
#pragma unroll
            for (int k = 0; k < KERW; k++) {
                float4 a = win[i + k];
                acc.x += a.x * wk[k].x; acc.y += a.y * wk[k].y;
                acc.z += a.z * wk[k].z; acc.w += a.w * wk[k].w;
            }
            acc.x = silu_f(acc.x); acc.y = silu_f(acc.y);
            acc.z = silu_f(acc.z); acc.w = silu_f(acc.w);
            acc = tf32r4(acc);
            *(float4*)(Ap + (tb * 8 + i) * CPAD + c4 * 4) = acc;
            *(float4*)(g_xr + (size_t)(t0 + i) * DM + d) = acc;
        }
    }

    CP_WAIT0();
    __syncthreads();

    const int gid = lane >> 2;
    const int tig = lane & 3;
    const int grp = lane >> 3;
    const int lr  = lane & 7;
    uint32_t aoffb[2];
#pragma unroll
    for (int mt = 0; mt < 2; mt++)
        aoffb[mt] = (uint32_t)(((warp_m * 32 + mt * 16 + (grp & 1) * 8 + lr) * CPAD
                                + (grp >> 1) * 4) * 4);
    uint32_t boff[3];
#pragma unroll
    for (int j = 0; j < 3; j++)
        boff[j] = (uint32_t)(((warp_n * 48 + (2 * j + (grp >> 1)) * 8 + lr) * PADS
                              + (grp & 1) * 4) * 4);

    float acc[2][6][4];
#pragma unroll
    for (int mt = 0; mt < 2; mt++)
#pragma unroll
        for (int nt = 0; nt < 6; nt++)
#pragma unroll
            for (int i = 0; i < 4; i++) acc[mt][nt][i] = 0.f;

#pragma unroll
    for (int t = 0; t < 4; t++) {
        const uint32_t bbase = sbB + (uint32_t)(t * ST_B96 * 4);
#pragma unroll
        for (int k0 = 0; k0 < 4; k0++) {
            uint32_t af[2][4];
#pragma unroll
            for (int mt = 0; mt < 2; mt++)
                ldsm4(af[mt][0], af[mt][1], af[mt][2], af[mt][3],
                      sbA + aoffb[mt] + (t * 32 + k0 * 8) * 4);
#pragma unroll
            for (int j = 0; j < 3; j++) {
                uint32_t b0, b1, b2, b3;
                ldsm4(b0, b1, b2, b3, bbase + boff[j] + k0 * 32);
#pragma unroll
                for (int mt = 0; mt < 2; mt++) {
                    mma_tf32(acc[mt][2 * j + 0], af[mt], b0, b1);
                    mma_tf32(acc[mt][2 * j + 1], af[mt], b2, b3);
                }
            }
        }
    }

    // ---- epilogue: accumulate into g_bcd via red.global ----
#pragma unroll
    for (int mt = 0; mt < 2; mt++) {
#pragma unroll
        for (int nt = 0; nt < 6; nt++) {
            int r0 = bm + warp_m * 32 + mt * 16 + gid;
            int cN = warp_n * 48 + nt * 8 + 2 * tig;
            atomicAdd(&g_bcd[(size_t)r0 * 96 + cN],       acc[mt][nt][0]);
            atomicAdd(&g_bcd[(size_t)r0 * 96 + cN + 1],   acc[mt][nt][1]);
            atomicAdd(&g_bcd[(size_t)(r0 + 8) * 96 + cN],     acc[mt][nt][2]);
            atomicAdd(&g_bcd[(size_t)(r0 + 8) * 96 + cN + 1], acc[mt][nt][3]);
        }
    }
}

// ---------------- prep: round operands, pack wbcd, zero g_bcd + counters -----
__global__ void prep_operands(
    const float4* __restrict__ seq,  const float4* __restrict__ win,
    const float4* __restrict__ wout, const float4* __restrict__ wd2,
    const float4* __restrict__ wb,   const float4* __restrict__ wc,
    const float4* __restrict__ wd1)
{
    const int n0 = TOK * DIN / 4;
    const int n1 = 2 * DM * DIN / 4;
    const int n2 = DIN * DM / 4;
    const int n3 = DM * DD / 4;
    const int n4 = 16 * DM / 4;
    const int n5 = 16 * DM / 4;
    const int n6 = 64 * DM / 4;
    const int n7 = TOK * 96 / 4;
    int i = blockIdx.x * 256 + threadIdx.x;
    if (i == 0) { g_sync1 = 0; g_sync2 = 0; }
    if (i < n0) { ((float4*)g_seq_r)[i] = tf32r4(seq[i]); return; }
    i -= n0;
    if (i < n1) { ((float4*)g_win_r)[i] = tf32r4(win[i]); return; }
    i -= n1;
    if (i < n2) { ((float4*)g_wout_r)[i] = tf32r4(wout[i]); return; }
    i -= n2;
    if (i < n3) { ((float4*)g_wd2_r)[i] = tf32r4(wd2[i]); return; }
    i -= n3;
    if (i < n4) { ((float4*)g_wbcd)[i] = tf32r4(wb[i]); return; }
    i -= n4;
    if (i < n5) { ((float4*)g_wbcd)[16 * DM / 4 + i] = tf32r4(wc[i]); return; }
    i -= n5;
    if (i < n6) { ((float4*)g_wbcd)[32 * DM / 4 + i] = tf32r4(wd1[i]); return; }
    i -= n6;
    if (i < n7) ((float4*)g_bcd)[i] = make_float4(0.f, 0.f, 0.f, 0.f);
}

// ---------------- fused SSM scan: phases 1+2+3 with software grid sync -------
// grid = (DM/128, NCH, BBATCH), 128 threads. All 512 CTAs fit in one wave
// (4 KB smem, 128 thr -> 16 CTAs/SM capacity), so atomic-counter barriers
// are deadlock-free. c==0 CTAs (16 of them = 2048 threads) run phase 2.
__global__ __launch_bounds__(128) void scan_fused(const float* __restrict__ Avec,
                                                  const float* __restrict__ Dvec)
{
    __shared__ float Bsm[CHUNK * 16];
    __shared__ float Csm[CHUNK * 16];
    const int tid = threadIdx.x;
    const int d = blockIdx.x * 128 + tid;
    const int c = blockIdx.y;
    const int b = blockIdx.z;
    const int base_tok = b * LL + c * CHUNK;
    const int cb = b * NCH + c;

    for (int i = tid; i < CHUNK * 16; i += 128) {
        int l = i >> 4, s = i & 15;
        Bsm[i] = g_bcd[(size_t)(base_tok + l) * 96 + s];
        Csm[i] = g_bcd[(size_t)(base_tok + l) * 96 + 16 + s];
    }
    __syncthreads();

    float E[16];
#pragma unroll
    for (int s = 0; s < 16; s++) E[s] = __expf(-Avec[d * 16 + s]);

    // ---- phase 1: local scan ----
    float h[16];
#pragma unroll
    for (int s = 0; s < 16; s++) h[s] = 0.f;
    float pd = 1.f;
    for (int l = 0; l < CHUNK; l++) {
        int tok = base_tok + l;
        float dl = g_delta[(size_t)tok * DM + d];
        float xv = g_xr[(size_t)tok * DM + d];
        float dx = dl * xv;
        pd *= dl;
#pragma unroll
        for (int s = 0; s < 16; s++)
            h[s] = E[s] * dl * h[s] + Bsm[l * 16 + s] * dx;
    }
    g_pd[(size_t)cb * DM + d] = pd;
#pragma unroll
    for (int s = 0; s < 16; s++)
        g_hend[((size_t)cb * 16 + s) * DM + d] = h[s];

    __threadfence();
    __syncthreads();
    if (tid == 0) atomicAdd(&g_sync1, 1);

    // ---- phase 2 (c==0 CTAs only: 16 x 128 = 2048 threads = (b,d) space) ----
    if (c == 0) {
        if (tid == 0) {
            while (*(volatile int*)&g_sync1 < SCAN_CTAS) { }
        }
        __syncthreads();
        __threadfence();

        float EC[16];
#pragma unroll
        for (int s = 0; s < 16; s++) EC[s] = __expf(-(float)CHUNK * Avec[d * 16 + s]);
        float carry[16];
#pragma unroll
        for (int s = 0; s < 16; s++) carry[s] = 0.f;
        for (int cc = 0; cc < NCH; cc++) {
            int cb2 = b * NCH + cc;
            float pd2 = g_pd[(size_t)cb2 * DM + d];
#pragma unroll
            for (int s = 0; s < 16; s++) {
                g_hinit[((size_t)cb2 * 16 + s) * DM + d] = carry[s];
                carry[s] = EC[s] * pd2 * carry[s] + g_hend[((size_t)cb2 * 16 + s) * DM + d];
            }
        }
        __threadfence();
        __syncthreads();
        if (tid == 0) atomicAdd(&g_sync2, 1);
    }

    // ---- wait for phase 2 ----
    if (tid == 0) {
        while (*(volatile int*)&g_sync2 < P2_CTAS) { }
    }
    __syncthreads();
    __threadfence();

    // ---- phase 3: replay with carry, fused gate + D ----
#pragma unroll
    for (int s = 0; s < 16; s++)
        h[s] = g_hinit[((size_t)cb * 16 + s) * DM + d];
    float Dd = Dvec[d];

    for (int l = 0; l < CHUNK; l++) {
        int tok = base_tok + l;
        float dl = g_delta[(size_t)tok * DM + d];
        float xv = g_xr[(size_t)tok * DM + d];
        float bg = g_ab[(size_t)tok * (2 * DM) + DM + d];
        float dx = dl * xv;
#pragma unroll
        for (int s = 0; s < 16; s++)
            h[s] = E[s] * dl * h[s] + Bsm[l * 16 + s] * dx;

        float y0 = 0.f, y1 = 0.f, y2 = 0.f, y3 = 0.f;
#pragma unroll
        for (int s = 0; s < 16; s += 4) {
            y0 += h[s + 0] * Csm[l * 16 + s + 0];
            y1 += h[s + 1] * Csm[l * 16 + s + 1];
            y2 += h[s + 2] * Csm[l * 16 + s + 2];
            y3 += h[s + 3] * Csm[l * 16 + s + 3];
        }
        float y = (y0 + y1) + (y2 + y3);
        g_obuf[(size_t)tok * DM + d] = tf32r((y + Dd * xv) * silu_f(bg));
    }
}

// ---------------- launch ------------------------------------------------------
#define SMEM_B128 ((BMT + 128) * PADS * 4 * 2)
#define SMEM_B64  ((BMT + 64) * PADS * 4 * 2)

extern "C" void kernel_launch(void* const* d_in, const int* in_sizes, int n_in,
                              void* d_out, int out_size)
{
    const float* seq    = (const float*)d_in[0];
    const float* W_in   = (const float*)d_in[1];
    const float* W_out  = (const float*)d_in[2];
    const float* W_B    = (const float*)d_in[3];
    const float* W_C    = (const float*)d_in[4];
    const float* W_D1   = (const float*)d_in[5];
    const float* W_D2   = (const float*)d_in[6];
    const float* conv_w = (const float*)d_in[7];
    const float* conv_b = (const float*)d_in[8];
    const float* Avec   = (const float*)d_in[9];
    const float* Dvec   = (const float*)d_in[10];
    float* out = (float*)d_out;

    float *ab, *bcd, *delta, *obuf, *seqr, *winr, *woutr, *wd2r;
    cudaGetSymbolAddress((void**)&ab,    g_ab);
    cudaGetSymbolAddress((void**)&bcd,   g_bcd);
    cudaGetSymbolAddress((void**)&delta, g_delta);
    cudaGetSymbolAddress((void**)&obuf,  g_obuf);
    cudaGetSymbolAddress((void**)&seqr,  g_seq_r);
    cudaGetSymbolAddress((void**)&winr,  g_win_r);
    cudaGetSymbolAddress((void**)&woutr, g_wout_r);
    cudaGetSymbolAddress((void**)&wd2r,  g_wd2_r);

    cudaFuncSetAttribute(gemm_mma<128>, cudaFuncAttributeMaxDynamicSharedMemorySize, SMEM_B128);
    cudaFuncSetAttribute(gemm_mma<64>,  cudaFuncAttributeMaxDynamicSharedMemorySize, SMEM_B64);
    cudaFuncSetAttribute(gemm_bcd_conv, cudaFuncAttributeMaxDynamicSharedMemorySize, SMEM_BCDCONV);

    // 0) prep: round operands, pack wbcd, zero g_bcd + sync counters
    const int ntot = TOK * DIN / 4 + 2 * DM * DIN / 4 + DIN * DM / 4 + DM * DD / 4
                   + 16 * DM / 4 + 16 * DM / 4 + 64 * DM / 4 + TOK * 96 / 4;
    prep_operands<<<(ntot + 255) / 256, 256>>>(
        (const float4*)seq, (const float4*)W_in, (const float4*)W_out,
        (const float4*)W_D2, (const float4*)W_B, (const float4*)W_C,
        (const float4*)W_D1);

    // 1) ab = seq @ W_in^T   (2048 x 2048 x 512)
    gemm_mma<128><<<dim3((2 * DM) / 128, TOK / BMT, 1), 256, SMEM_B128>>>(
        seqr, DIN, winr, DIN, ab, 2 * DM, 2 * DM, DIN / BKT, 0, 0, 0, nullptr);

    // 2) fused conv+SiLU + bcd GEMM (split-K=8, atomic accumulate into g_bcd)
    gemm_bcd_conv<<<dim3(1, TOK / 128, KSPLIT_BCD), 256, SMEM_BCDCONV>>>(conv_w, conv_b);

    // 3) delta = softplus(D + xd1 @ W_D2^T)  (2048 x 1024 x 64), BNT=64
    gemm_mma<64><<<dim3(DM / 64, TOK / BMT, 1), 256, SMEM_B64>>>(
        bcd + 32, 96, wd2r, DD, delta, DM, DM, DD / BKT, 0, 0, 1, Dvec);

    // 4) fused 3-phase scan (software grid sync)
    scan_fused<<<dim3(DM / 128, NCH, BBATCH), 128>>>(Avec, Dvec);

    // 5) out = obuf @ W_out^T  (2048 x 512 x 1024)
    gemm_mma<64><<<dim3(DIN / 64, TOK / BMT, 1), 256, SMEM_B64>>>(
        obuf, DM, woutr, DM, out, DIN, DIN, DM / BKT, 0, 0, 0, nullptr);
}

// round 17
// speedup vs baseline: 1.0957x; 1.0067x over previous
#include <cuda_runtime.h>
#include <math.h>
#include <cstdint>

// ---------------- problem constants ------------------------------------------
#define BBATCH 2
#define LL 1024
#define DIN 512
#define DM 1024
#define DS 16
#define DD 64
#define KERW 4
#define TOK (BBATCH * LL)      // 2048
#define CHUNK 32
#define NCH (LL / CHUNK)       // 32
#define KSPLIT_BCD 8
#define SCAN_CTAS ((DM / 128) * NCH * BBATCH)   // 512
#define P2_CTAS   ((DM / 128) * BBATCH)         // 16

// ---------------- scratch (static device globals) ----------------------------
__device__ __align__(16) float g_ab[TOK * 2 * DM];
__device__ __align__(16) float g_xr[TOK * DM];       // tf32-rounded conv output
__device__ __align__(16) float g_bcd[TOK * 96];      // atomically accumulated
__device__ __align__(16) float g_delta[TOK * DM];
__device__ __align__(16) float g_wbcd[96 * DM];
__device__ __align__(16) float g_hend[BBATCH * NCH * DS * DM];
__device__ __align__(16) float g_pd[BBATCH * NCH * DM];
__device__ __align__(16) float g_hinit[BBATCH * NCH * DS * DM];
__device__ __align__(16) float g_obuf[TOK * DM];
__device__ int g_sync1;
__device__ int g_sync2;
// tf32-rounded copies of GEMM operands
__device__ __align__(16) float g_seq_r[TOK * DIN];
__device__ __align__(16) float g_win_r[2 * DM * DIN];
__device__ __align__(16) float g_wout_r[DIN * DM];
__device__ __align__(16) float g_wd2_r[DM * DD];

// ---------------- small PTX helpers ------------------------------------------
__device__ __forceinline__ uint32_t smem_u32(const void* p) {
    uint32_t a;
    asm("{ .reg .u64 t; cvta.to.shared.u64 t, %1; cvt.u32.u64 %0, t; }" : "=r"(a) : "l"(p));
    return a;
}
__device__ __forceinline__ float tf32r(float x) {
    uint32_t o;
    asm("cvt.rna.tf32.f32 %0, %1;" : "=r"(o) : "f"(x));
    return __uint_as_float(o);
}
__device__ __forceinline__ float4 tf32r4(float4 v) {
    return make_float4(tf32r(v.x), tf32r(v.y), tf32r(v.z), tf32r(v.w));
}
__device__ __forceinline__ void cp16(uint32_t dst, const void* src, int sz) {
    asm volatile("cp.async.ca.shared.global [%0], [%1], 16, %2;"
                 :: "r"(dst), "l"(src), "r"(sz) : "memory");
}
#define CP_COMMIT() asm volatile("cp.async.commit_group;" ::: "memory")
#define CP_WAIT0()  asm volatile("cp.async.wait_group 0;" ::: "memory")

// fast softplus / silu (MUFU-based intrinsics; rel err ~1e-7, far under budget)
__device__ __forceinline__ float softplus_f(float z) {
    return fmaxf(z, 0.f) + __logf(1.f + __expf(-fabsf(z)));
}
__device__ __forceinline__ float silu_f(float x) {
    return __fdividef(x, 1.f + __expf(-x));
}

__device__ __forceinline__ void mma_tf32(float* c, const uint32_t* a, uint32_t b0, uint32_t b1) {
    asm volatile(
        "mma.sync.aligned.m16n8k8.row.col.f32.tf32.tf32.f32 "
        "{%0,%1,%2,%3}, {%4,%5,%6,%7}, {%8,%9}, {%0,%1,%2,%3};"
        : "+f"(c[0]), "+f"(c[1]), "+f"(c[2]), "+f"(c[3])
        : "r"(a[0]), "r"(a[1]), "r"(a[2]), "r"(a[3]), "r"(b0), "r"(b1));
}
__device__ __forceinline__ void ldsm4(uint32_t& r0, uint32_t& r1, uint32_t& r2, uint32_t& r3,
                                      uint32_t addr) {
    asm volatile("ldmatrix.sync.aligned.m8n8.x4.shared.b16 {%0,%1,%2,%3}, [%4];"
                 : "=r"(r0), "=r"(r1), "=r"(r2), "=r"(r3) : "r"(addr));
}

// ---------------- generic tf32 GEMM:  C[M,N] = A[M,K] * W[N,K]^T -------------
// Pre-rounded tf32 operands; cvt-free ldmatrix mainloop.
// __launch_bounds__(256, 2): cap regs so 2 CTAs/SM co-reside (grid=256 GEMMs
// run in ONE wave instead of two).
#define BMT 128
#define BKT 32
#define PADS 36

// mode: 0 = plain store, 1 = softplus(aux[col] + acc)
template <int BNT>
__global__ __launch_bounds__(256, 2) void gemm_mma(
    const float* __restrict__ A, int lda,
    const float* __restrict__ W, int ldw,
    float* __restrict__ C, int ldc,
    int Nvalid, int T, int kstride, long cstride,
    int mode, const float* __restrict__ aux)
{
    constexpr int NT = BNT / 16;
    constexpr int stA = BMT * PADS;
    constexpr int stB = BNT * PADS;

    extern __shared__ float smem[];
    float* As = smem;
    float* Bs = smem + 2 * stA;
    const uint32_t sbA = smem_u32(As);
    const uint32_t sbB = smem_u32(Bs);

    const int tid = threadIdx.x;
    const int lane = tid & 31;
    const int wid = tid >> 5;
    const int warp_m = wid & 3;
    const int warp_n = wid >> 2;
    const int bm = blockIdx.y * BMT;
    const int bn = blockIdx.x * BNT;
    const int koff = blockIdx.z * kstride;
    C += (long)blockIdx.z * cstride;

    const int gid = lane >> 2;
    const int tig = lane & 3;
    const int grp = lane >> 3;
    const int lr  = lane & 7;

    uint32_t aoff[2];
#pragma unroll
    for (int mt = 0; mt < 2; mt++)
        aoff[mt] = (uint32_t)(((warp_m * 32 + mt * 16 + (grp & 1) * 8 + lr) * PADS
                               + (grp >> 1) * 4) * 4);
    uint32_t boff[NT / 2];
#pragma unroll
    for (int j = 0; j < NT / 2; j++)
        boff[j] = (uint32_t)(((warp_n * (BNT / 2) + (2 * j + (grp >> 1)) * 8 + lr) * PADS
                              + (grp & 1) * 4) * 4);

    float acc[2][NT][4];
#pragma unroll
    for (int mt = 0; mt < 2; mt++)
#pragma unroll
        for (int nt = 0; nt < NT; nt++)
#pragma unroll
            for (int i = 0; i < 4; i++) acc[mt][nt][i] = 0.f;

    auto load_tiles = [&](int st, int t) {
        const int kc = koff + t * BKT;
#pragma unroll
        for (int j = 0; j < (BMT * 8) / 256; j++) {
            int idx = tid + j * 256;
            int row = idx >> 3, c4 = idx & 7;
            cp16(sbA + (uint32_t)(st * stA + row * PADS + c4 * 4) * 4,
                 A + (size_t)(bm + row) * lda + kc + c4 * 4, 16);
        }
#pragma unroll
        for (int j = 0; j < (BNT * 8 + 255) / 256; j++) {
            int idx = tid + j * 256;
            if (idx < BNT * 8) {
                int row = idx >> 3, c4 = idx & 7;
                bool v = (bn + row) < Nvalid;
                cp16(sbB + (uint32_t)(st * stB + row * PADS + c4 * 4) * 4,
                     W + (size_t)(v ? bn + row : 0) * ldw + kc + c4 * 4, v ? 16 : 0);
            }
        }
    };

    load_tiles(0, 0);
    CP_COMMIT();

    for (int t = 0; t < T; t++) {
        CP_WAIT0();
        __syncthreads();
        if (t + 1 < T) { load_tiles((t + 1) & 1, t + 1); CP_COMMIT(); }

        const uint32_t abase = sbA + (uint32_t)((t & 1) * stA * 4);
        const uint32_t bbase = sbB + (uint32_t)((t & 1) * stB * 4);
#pragma unroll
        for (int k0 = 0; k0 < 4; k0++) {
            uint32_t af[2][4];
#pragma unroll
            for (int mt = 0; mt < 2; mt++)
                ldsm4(af[mt][0], af[mt][1], af[mt][2], af[mt][3],
                      abase + aoff[mt] + k0 * 32);
#pragma unroll
            for (int j = 0; j < NT / 2; j++) {
                uint32_t b0, b1, b2, b3;
                ldsm4(b0, b1, b2, b3, bbase + boff[j] + k0 * 32);
#pragma unroll
                for (int mt = 0; mt < 2; mt++) {
                    mma_tf32(acc[mt][2 * j + 0], af[mt], b0, b1);
                    mma_tf32(acc[mt][2 * j + 1], af[mt], b2, b3);
                }
            }
        }
    }

    // ---- epilogue ----
#pragma unroll
    for (int mt = 0; mt < 2; mt++) {
#pragma unroll
        for (int nt = 0; nt < NT; nt++) {
            int r0 = bm + warp_m * 32 + mt * 16 + gid;
            int cN = bn + warp_n * (BNT / 2) + nt * 8 + 2 * tig;
            if (cN < Nvalid) {
                float v0 = acc[mt][nt][0], v1 = acc[mt][nt][1];
                float v2 = acc[mt][nt][2], v3 = acc[mt][nt][3];
                if (mode == 1) {
                    float d0 = aux[cN], d1 = aux[cN + 1];
                    v0 = softplus_f(d0 + v0);
                    v1 = softplus_f(d1 + v1);
                    v2 = softplus_f(d0 + v2);
                    v3 = softplus_f(d1 + v3);
                }
                *(float2*)&C[(size_t)r0 * ldc + cN] = make_float2(v0, v1);
                *(float2*)&C[(size_t)(r0 + 8) * ldc + cN] = make_float2(v2, v3);
            }
        }
    }
}

// ---------------- fused conv+SiLU + bcd GEMM (N=96, T=4, split-K over d) -----
#define CPAD 132
#define ST_B96 (96 * PADS)
#define SMEM_BCDCONV ((128 * CPAD + 4 * ST_B96) * 4)

__global__ __launch_bounds__(256) void gemm_bcd_conv(
    const float* __restrict__ cw, const float* __restrict__ cb)
{
    extern __shared__ float smem[];
    float* Ap = smem;                        // [128][CPAD]
    float* Bs = smem + 128 * CPAD;           // [4][96][PADS]
    const uint32_t sbA = smem_u32(Ap);
    const uint32_t sbB = smem_u32(Bs);

    const int tid = threadIdx.x;
    const int lane = tid & 31;
    const int wid = tid >> 5;
    const int warp_m = wid & 3;
    const int warp_n = wid >> 2;
    const int bm = blockIdx.y * 128;
    const int koff = blockIdx.z * (DM / KSPLIT_BCD);

    // ---- prologue: prefetch ALL 4 B k-tiles ----
#pragma unroll
    for (int t = 0; t < 4; t++) {
        const int kc = koff + t * BKT;
#pragma unroll
        for (int j = 0; j < 3; j++) {
            int idx = tid + j * 256;
            if (idx < 96 * 8) {
                int row = idx >> 3, c4 = idx & 7;
                cp16(sbB + (uint32_t)(t * ST_B96 + row * PADS + c4 * 4) * 4,
                     g_wbcd + (size_t)row * DM + kc + c4 * 4, 16);
            }
        }
        CP_COMMIT();
    }

    // ---- conv phase ----
    for (int task = tid; task < 512; task += 256) {
        int c4 = task & 31;
        int tb = task >> 5;
        int t0 = bm + tb * 8;
        int l0 = t0 & (LL - 1);
        int base = t0 - l0;
        int d = koff + c4 * 4;

        float4 cb4 = *(const float4*)(cb + d);
        float4 w0 = *(const float4*)(cw + (d + 0) * KERW);
        float4 w1 = *(const float4*)(cw + (d + 1) * KERW);
        float4 w2 = *(const float4*)(cw + (d + 2) * KERW);
        float4 w3 = *(const float4*)(cw + (d + 3) * KERW);
        float4 wk[KERW];
        wk[0] = make_float4(w0.x, w1.x, w2.x, w3.x);
        wk[1] = make_float4(w0.y, w1.y, w2.y, w3.y);
        wk[2] = make_float4(w0.z, w1.z, w2.z, w3.z);
        wk[3] = make_float4(w0.w, w1.w, w2.w, w3.w);

        float4 win[8 + KERW - 1];
#pragma unroll
        for (int j = 0; j < 8 + KERW - 1; j++) {
            int ll = l0 - (KERW - 1) + j;
            if (ll >= 0)
                win[j] = *(const float4*)(g_ab + (size_t)(base + ll) * (2 * DM) + d);
            else
                win[j] = make_float4(0.f, 0.f, 0.f, 0.f);
        }
#pragma unroll
        for (int i = 0; i < 8; i++) {
            float4 acc = cb4;
#pragma unroll
            for (int k = 0; k < KERW; k++) {
                float4 a = win[i + k];
                acc.x += a.x * wk[k].x; acc.y += a.y * wk[k].y;
                acc.z += a.z * wk[k].z; acc.w += a.w * wk[k].w;
            }
            acc.x = silu_f(acc.x); acc.y = silu_f(acc.y);
            acc.z = silu_f(acc.z); acc.w = silu_f(acc.w);
            acc = tf32r4(acc);
            *(float4*)(Ap + (tb * 8 + i) * CPAD + c4 * 4) = acc;
            *(float4*)(g_xr + (size_t)(t0 + i) * DM + d) = acc;
        }
    }

    CP_WAIT0();
    __syncthreads();

    const int gid = lane >> 2;
    const int tig = lane & 3;
    const int grp = lane >> 3;
    const int lr  = lane & 7;
    uint32_t aoffb[2];
#pragma unroll
    for (int mt = 0; mt < 2; mt++)
        aoffb[mt] = (uint32_t)(((warp_m * 32 + mt * 16 + (grp & 1) * 8 + lr) * CPAD
                                + (grp >> 1) * 4) * 4);
    uint32_t boff[3];
#pragma unroll
    for (int j = 0; j < 3; j++)
        boff[j] = (uint32_t)(((warp_n * 48 + (2 * j + (grp >> 1)) * 8 + lr) * PADS
                              + (grp & 1) * 4) * 4);

    float acc[2][6][4];
#pragma unroll
    for (int mt = 0; mt < 2; mt++)
#pragma unroll
        for (int nt = 0; nt < 6; nt++)
#pragma unroll
            for (int i = 0; i < 4; i++) acc[mt][nt][i] = 0.f;

#pragma unroll
    for (int t = 0; t < 4; t++) {
        const uint32_t bbase = sbB + (uint32_t)(t * ST_B96 * 4);
#pragma unroll
        for (int k0 = 0; k0 < 4; k0++) {
            uint32_t af[2][4];
#pragma unroll
            for (int mt = 0; mt < 2; mt++)
                ldsm4(af[mt][0], af[mt][1], af[mt][2], af[mt][3],
                      sbA + aoffb[mt] + (t * 32 + k0 * 8) * 4);
#pragma unroll
            for (int j = 0; j < 3; j++) {
                uint32_t b0, b1, b2, b3;
                ldsm4(b0, b1, b2, b3, bbase + boff[j] + k0 * 32);
#pragma unroll
                for (int mt = 0; mt < 2; mt++) {
                    mma_tf32(acc[mt][2 * j + 0], af[mt], b0, b1);
                    mma_tf32(acc[mt][2 * j + 1], af[mt], b2, b3);
                }
            }
        }
    }

    // ---- epilogue: accumulate into g_bcd via red.global ----
#pragma unroll
    for (int mt = 0; mt < 2; mt++) {
#pragma unroll
        for (int nt = 0; nt < 6; nt++) {
            int r0 = bm + warp_m * 32 + mt * 16 + gid;
            int cN = warp_n * 48 + nt * 8 + 2 * tig;
            atomicAdd(&g_bcd[(size_t)r0 * 96 + cN],       acc[mt][nt][0]);
            atomicAdd(&g_bcd[(size_t)r0 * 96 + cN + 1],   acc[mt][nt][1]);
            atomicAdd(&g_bcd[(size_t)(r0 + 8) * 96 + cN],     acc[mt][nt][2]);
            atomicAdd(&g_bcd[(size_t)(r0 + 8) * 96 + cN + 1], acc[mt][nt][3]);
        }
    }
}

// ---------------- prep: round operands, pack wbcd, zero g_bcd + counters -----
__global__ void prep_operands(
    const float4* __restrict__ seq,  const float4* __restrict__ win,
    const float4* __restrict__ wout, const float4* __restrict__ wd2,
    const float4* __restrict__ wb,   const float4* __restrict__ wc,
    const float4* __restrict__ wd1)
{
    const int n0 = TOK * DIN / 4;
    const int n1 = 2 * DM * DIN / 4;
    const int n2 = DIN * DM / 4;
    const int n3 = DM * DD / 4;
    const int n4 = 16 * DM / 4;
    const int n5 = 16 * DM / 4;
    const int n6 = 64 * DM / 4;
    const int n7 = TOK * 96 / 4;
    int i = blockIdx.x * 256 + threadIdx.x;
    if (i == 0) { g_sync1 = 0; g_sync2 = 0; }
    if (i < n0) { ((float4*)g_seq_r)[i] = tf32r4(seq[i]); return; }
    i -= n0;
    if (i < n1) { ((float4*)g_win_r)[i] = tf32r4(win[i]); return; }
    i -= n1;
    if (i < n2) { ((float4*)g_wout_r)[i] = tf32r4(wout[i]); return; }
    i -= n2;
    if (i < n3) { ((float4*)g_wd2_r)[i] = tf32r4(wd2[i]); return; }
    i -= n3;
    if (i < n4) { ((float4*)g_wbcd)[i] = tf32r4(wb[i]); return; }
    i -= n4;
    if (i < n5) { ((float4*)g_wbcd)[16 * DM / 4 + i] = tf32r4(wc[i]); return; }
    i -= n5;
    if (i < n6) { ((float4*)g_wbcd)[32 * DM / 4 + i] = tf32r4(wd1[i]); return; }
    i -= n6;
    if (i < n7) ((float4*)g_bcd)[i] = make_float4(0.f, 0.f, 0.f, 0.f);
}

// ---------------- fused SSM scan: phases 1+2+3 with software grid sync -------
__global__ __launch_bounds__(128) void scan_fused(const float* __restrict__ Avec,
                                                  const float* __restrict__ Dvec)
{
    __shared__ float Bsm[CHUNK * 16];
    __shared__ float Csm[CHUNK * 16];
    const int tid = threadIdx.x;
    const int d = blockIdx.x * 128 + tid;
    const int c = blockIdx.y;
    const int b = blockIdx.z;
    const int base_tok = b * LL + c * CHUNK;
    const int cb = b * NCH + c;

    for (int i = tid; i < CHUNK * 16; i += 128) {
        int l = i >> 4, s = i & 15;
        Bsm[i] = g_bcd[(size_t)(base_tok + l) * 96 + s];
        Csm[i] = g_bcd[(size_t)(base_tok + l) * 96 + 16 + s];
    }
    __syncthreads();

    float E[16];
#pragma unroll
    for (int s = 0; s < 16; s++) E[s] = __expf(-Avec[d * 16 + s]);

    // ---- phase 1: local scan ----
    float h[16];
#pragma unroll
    for (int s = 0; s < 16; s++) h[s] = 0.f;
    float pd = 1.f;
    for (int l = 0; l < CHUNK; l++) {
        int tok = base_tok + l;
        float dl = g_delta[(size_t)tok * DM + d];
        float xv = g_xr[(size_t)tok * DM + d];
        float dx = dl * xv;
        pd *= dl;
#pragma unroll
        for (int s = 0; s < 16; s++)
            h[s] = E[s] * dl * h[s] + Bsm[l * 16 + s] * dx;
    }
    g_pd[(size_t)cb * DM + d] = pd;
#pragma unroll
    for (int s = 0; s < 16; s++)
        g_hend[((size_t)cb * 16 + s) * DM + d] = h[s];

    __threadfence();
    __syncthreads();
    if (tid == 0) atomicAdd(&g_sync1, 1);

    // ---- phase 2 (c==0 CTAs only: 16 x 128 = 2048 threads = (b,d) space) ----
    if (c == 0) {
        if (tid == 0) {
            while (*(volatile int*)&g_sync1 < SCAN_CTAS) { }
        }
        __syncthreads();
        __threadfence();

        float EC[16];
#pragma unroll
        for (int s = 0; s < 16; s++) EC[s] = __expf(-(float)CHUNK * Avec[d * 16 + s]);
        float carry[16];
#pragma unroll
        for (int s = 0; s < 16; s++) carry[s] = 0.f;
        for (int cc = 0; cc < NCH; cc++) {
            int cb2 = b * NCH + cc;
            float pd2 = g_pd[(size_t)cb2 * DM + d];
#pragma unroll
            for (int s = 0; s < 16; s++) {
                g_hinit[((size_t)cb2 * 16 + s) * DM + d] = carry[s];
                carry[s] = EC[s] * pd2 * carry[s] + g_hend[((size_t)cb2 * 16 + s) * DM + d];
            }
        }
        __threadfence();
        __syncthreads();
        if (tid == 0) atomicAdd(&g_sync2, 1);
    }

    // ---- wait for phase 2 ----
    if (tid == 0) {
        while (*(volatile int*)&g_sync2 < P2_CTAS) { }
    }
    __syncthreads();
    __threadfence();

    // ---- phase 3: replay with carry, fused gate + D ----
#pragma unroll
    for (int s = 0; s < 16; s++)
        h[s] = g_hinit[((size_t)cb * 16 + s) * DM + d];
    float Dd = Dvec[d];

    for (int l = 0; l < CHUNK; l++) {
        int tok = base_tok + l;
        float dl = g_delta[(size_t)tok * DM + d];
        float xv = g_xr[(size_t)tok * DM + d];
        float bg = g_ab[(size_t)tok * (2 * DM) + DM + d];
        float dx = dl * xv;
#pragma unroll
        for (int s = 0; s < 16; s++)
            h[s] = E[s] * dl * h[s] + Bsm[l * 16 + s] * dx;

        float y0 = 0.f, y1 = 0.f, y2 = 0.f, y3 = 0.f;
#pragma unroll
        for (int s = 0; s < 16; s += 4) {
            y0 += h[s + 0] * Csm[l * 16 + s + 0];
            y1 += h[s + 1] * Csm[l * 16 + s + 1];
            y2 += h[s + 2] * Csm[l * 16 + s + 2];
            y3 += h[s + 3] * Csm[l * 16 + s + 3];
        }
        float y = (y0 + y1) + (y2 + y3);
        g_obuf[(size_t)tok * DM + d] = tf32r((y + Dd * xv) * silu_f(bg));
    }
}

// ---------------- launch ------------------------------------------------------
#define SMEM_B128 ((BMT + 128) * PADS * 4 * 2)
#define SMEM_B64  ((BMT + 64) * PADS * 4 * 2)

extern "C" void kernel_launch(void* const* d_in, const int* in_sizes, int n_in,
                              void* d_out, int out_size)
{
    const float* seq    = (const float*)d_in[0];
    const float* W_in   = (const float*)d_in[1];
    const float* W_out  = (const float*)d_in[2];
    const float* W_B    = (const float*)d_in[3];
    const float* W_C    = (const float*)d_in[4];
    const float* W_D1   = (const float*)d_in[5];
    const float* W_D2   = (const float*)d_in[6];
    const float* conv_w = (const float*)d_in[7];
    const float* conv_b = (const float*)d_in[8];
    const float* Avec   = (const float*)d_in[9];
    const float* Dvec   = (const float*)d_in[10];
    float* out = (float*)d_out;

    float *ab, *bcd, *delta, *obuf, *seqr, *winr, *woutr, *wd2r;
    cudaGetSymbolAddress((void**)&ab,    g_ab);
    cudaGetSymbolAddress((void**)&bcd,   g_bcd);
    cudaGetSymbolAddress((void**)&delta, g_delta);
    cudaGetSymbolAddress((void**)&obuf,  g_obuf);
    cudaGetSymbolAddress((void**)&seqr,  g_seq_r);
    cudaGetSymbolAddress((void**)&winr,  g_win_r);
    cudaGetSymbolAddress((void**)&woutr, g_wout_r);
    cudaGetSymbolAddress((void**)&wd2r,  g_wd2_r);

    cudaFuncSetAttribute(gemm_mma<128>, cudaFuncAttributeMaxDynamicSharedMemorySize, SMEM_B128);
    cudaFuncSetAttribute(gemm_mma<64>,  cudaFuncAttributeMaxDynamicSharedMemorySize, SMEM_B64);
    cudaFuncSetAttribute(gemm_bcd_conv, cudaFuncAttributeMaxDynamicSharedMemorySize, SMEM_BCDCONV);

    // 0) prep: round operands, pack wbcd, zero g_bcd + sync counters
    const int ntot = TOK * DIN / 4 + 2 * DM * DIN / 4 + DIN * DM / 4 + DM * DD / 4
                   + 16 * DM / 4 + 16 * DM / 4 + 64 * DM / 4 + TOK * 96 / 4;
    prep_operands<<<(ntot + 255) / 256, 256>>>(
        (const float4*)seq, (const float4*)W_in, (const float4*)W_out,
        (const float4*)W_D2, (const float4*)W_B, (const float4*)W_C,
        (const float4*)W_D1);

    // 1) ab = seq @ W_in^T   (2048 x 2048 x 512)
    gemm_mma<128><<<dim3((2 * DM) / 128, TOK / BMT, 1), 256, SMEM_B128>>>(
        seqr, DIN, winr, DIN, ab, 2 * DM, 2 * DM, DIN / BKT, 0, 0, 0, nullptr);

    // 2) fused conv+SiLU + bcd GEMM (split-K=8, atomic accumulate into g_bcd)
    gemm_bcd_conv<<<dim3(1, TOK / 128, KSPLIT_BCD), 256, SMEM_BCDCONV>>>(conv_w, conv_b);

    // 3) delta = softplus(D + xd1 @ W_D2^T)  (2048 x 1024 x 64), BNT=64
    gemm_mma<64><<<dim3(DM / 64, TOK / BMT, 1), 256, SMEM_B64>>>(
        bcd + 32, 96, wd2r, DD, delta, DM, DM, DD / BKT, 0, 0, 1, Dvec);

    // 4) fused 3-phase scan (software grid sync)
    scan_fused<<<dim3(DM / 128, NCH, BBATCH), 128>>>(Avec, Dvec);

    // 5) out = obuf @ W_out^T  (2048 x 512 x 1024)
    gemm_mma<64><<<dim3(DIN / 64, TOK / BMT, 1), 256, SMEM_B64>>>(
        obuf, DM, woutr, DM, out, DIN, DIN, DM / BKT, 0, 0, 0, nullptr);
}